// round 6
// baseline (speedup 1.0000x reference)
#include <cuda_runtime.h>
#include <cuda_bf16.h>
#include <cstdint>

#define BATCH 4
#define SEQ   2048
#define DIM   1024
#define MTOT  (BATCH*SEQ)

// ------------------------- device scratch (no allocs) -----------------------
__device__ __nv_bfloat16 Xhi[MTOT*(size_t)DIM];
__device__ __nv_bfloat16 Xlo[MTOT*(size_t)DIM];
__device__ __nv_bfloat16 Wthi[3*(size_t)DIM*DIM];   // [z][n][k]
__device__ __nv_bfloat16 Wtlo[3*(size_t)DIM*DIM];
__device__ __nv_bfloat16 Qhi[MTOT*(size_t)DIM];
__device__ __nv_bfloat16 Qlo[MTOT*(size_t)DIM];
__device__ __nv_bfloat16 Khi[MTOT*(size_t)DIM];
__device__ __nv_bfloat16 Klo[MTOT*(size_t)DIM];
__device__ __nv_bfloat16 Vhi[MTOT*(size_t)DIM];
__device__ __nv_bfloat16 Vlo[MTOT*(size_t)DIM];
__device__ __nv_bfloat16 Vthi[MTOT*(size_t)DIM];    // [b][d][s]
__device__ __nv_bfloat16 Vtlo[MTOT*(size_t)DIM];
__device__ float         Sg  [(size_t)BATCH*SEQ*SEQ];   // [b][q][k]
__device__ __nv_bfloat16 Phi [(size_t)BATCH*SEQ*SEQ];
__device__ __nv_bfloat16 Plo [(size_t)BATCH*SEQ*SEQ];

// ------------------------------ helpers -------------------------------------
__device__ __forceinline__ uint32_t smem_to_u32(const void* p) {
    uint32_t a;
    asm("{ .reg .u64 t; cvta.to.shared.u64 t, %1; cvt.u32.u64 %0, t; }"
        : "=r"(a) : "l"(p));
    return a;
}
// 64B-row swizzle: bits[5:4] ^= bits[8:7]
#define SW64(off) ((off) ^ (((off) >> 3) & 0x30))

__device__ __forceinline__ void ldsm_x4(uint32_t* r, uint32_t addr) {
    asm volatile("ldmatrix.sync.aligned.m8n8.x4.shared.b16 {%0,%1,%2,%3}, [%4];"
                 : "=r"(r[0]), "=r"(r[1]), "=r"(r[2]), "=r"(r[3]) : "r"(addr));
}
__device__ __forceinline__ void mma_bf16(float* c, const uint32_t* a, const uint32_t* b) {
    asm volatile(
        "mma.sync.aligned.m16n8k16.row.col.f32.bf16.bf16.f32 "
        "{%0,%1,%2,%3}, {%4,%5,%6,%7}, {%8,%9}, {%0,%1,%2,%3};"
        : "+f"(c[0]), "+f"(c[1]), "+f"(c[2]), "+f"(c[3])
        : "r"(a[0]), "r"(a[1]), "r"(a[2]), "r"(a[3]), "r"(b[0]), "r"(b[1]));
}
__device__ __forceinline__ void cp16(uint32_t smem_dst, const void* gptr) {
    asm volatile("cp.async.cg.shared.global [%0], [%1], 16;"
                 :: "r"(smem_dst), "l"(gptr));
}

// ----------------- 4-stage bf16x3 mainloop -----------------------------------
// Block tile 128m x 128n x 32k. 8 warps: 2(m) x 4(n), warp tile 64x32.
// Stage (32 KB): Ah[8K] Al[8K] Bh[8K] Bl[8K]; rows are 64B, SW64 swizzled.
#define ST_AH 0
#define ST_AL 8192
#define ST_BH 16384
#define ST_BL 24576
#define STAGE 32768
#define NSTAGE 4
#define GEMM_SMEM (NSTAGE*STAGE)   // 131072

__device__ __forceinline__ void gemm_tile_db(
    const __nv_bfloat16* __restrict__ Ah, const __nv_bfloat16* __restrict__ Al, int lda,
    const __nv_bfloat16* __restrict__ Bh, const __nv_bfloat16* __restrict__ Bl, int ldb,
    int kIters, char* smem, float acc[4][4][4])
{
    const int tid = threadIdx.x;
    const int wid = tid >> 5, lane = tid & 31;
    const int wm = (wid & 1) * 64;     // warp m offset
    const int wn = (wid >> 1) * 32;    // warp n offset
    const uint32_t sbase = smem_to_u32(smem);

    // cp.async geometry: thread covers rows r0 and r0+64, 16B chunk c4
    const int r0 = tid >> 2, c4 = tid & 3;
    const uint32_t so0 = SW64((uint32_t)(r0 * 64 + c4 * 16));
    const size_t gA0 = (size_t)r0 * lda + c4 * 8;
    const size_t gB0 = (size_t)r0 * ldb + c4 * 8;
    const size_t gA1 = gA0 + (size_t)64 * lda;
    const size_t gB1 = gB0 + (size_t)64 * ldb;

    auto issue = [&](int c) {
        const uint32_t st = sbase + (uint32_t)(c % NSTAGE) * STAGE;
        const int kc = c * 32;
        cp16(st + ST_AH + so0,        Ah + gA0 + kc);
        cp16(st + ST_AH + so0 + 4096, Ah + gA1 + kc);
        cp16(st + ST_AL + so0,        Al + gA0 + kc);
        cp16(st + ST_AL + so0 + 4096, Al + gA1 + kc);
        cp16(st + ST_BH + so0,        Bh + gB0 + kc);
        cp16(st + ST_BH + so0 + 4096, Bh + gB1 + kc);
        cp16(st + ST_BL + so0,        Bl + gB0 + kc);
        cp16(st + ST_BL + so0 + 4096, Bl + gB1 + kc);
        asm volatile("cp.async.commit_group;" ::: "memory");
    };

    // ldmatrix swizzled per-thread bases (row bits 1..2 come only from lane bits,
    // so wm/wn/mi/p offsets compose additively; k-step (bit 5) composes by XOR)
    const uint32_t aswz = SW64((uint32_t)((lane & 15) * 64 + ((lane >> 4) & 1) * 16))
                          + (uint32_t)wm * 64;
    const uint32_t bswz = SW64((uint32_t)((((lane & 7) + ((lane >> 4) & 1) * 8)) * 64
                                          + ((lane >> 3) & 1) * 16))
                          + (uint32_t)wn * 64;

    issue(0);
    if (kIters > 1) issue(1);
    if (kIters > 2) issue(2);

    for (int c = 0; c < kIters; c++) {
        const int rem = kIters - 1 - c;
        if (rem >= 2)      asm volatile("cp.async.wait_group 2;" ::: "memory");
        else if (rem == 1) asm volatile("cp.async.wait_group 1;" ::: "memory");
        else               asm volatile("cp.async.wait_group 0;" ::: "memory");
        __syncthreads();
        if (c + 3 < kIters) issue(c + 3);

        const uint32_t st = sbase + (uint32_t)(c % NSTAGE) * STAGE;
        #pragma unroll
        for (int ks = 0; ks < 2; ks++) {
            const uint32_t ko = (uint32_t)ks * 32;
            uint32_t ah[4][4], bh[4][2], bl[4][2], t[4];
            #pragma unroll
            for (int p = 0; p < 2; p++) {
                ldsm_x4(t, (st + ST_BH + bswz + p * 1024) ^ ko);
                bh[2*p][0] = t[0]; bh[2*p][1] = t[1];
                bh[2*p+1][0] = t[2]; bh[2*p+1][1] = t[3];
            }
            #pragma unroll
            for (int mi = 0; mi < 4; mi++)
                ldsm_x4(ah[mi], (st + ST_AH + aswz + mi * 1024) ^ ko);
            #pragma unroll
            for (int mi = 0; mi < 4; mi++)
                #pragma unroll
                for (int ni = 0; ni < 4; ni++)
                    mma_bf16(acc[mi][ni], ah[mi], bh[ni]);     // hi * hi
            #pragma unroll
            for (int p = 0; p < 2; p++) {
                ldsm_x4(t, (st + ST_BL + bswz + p * 1024) ^ ko);
                bl[2*p][0] = t[0]; bl[2*p][1] = t[1];
                bl[2*p+1][0] = t[2]; bl[2*p+1][1] = t[3];
            }
            #pragma unroll
            for (int mi = 0; mi < 4; mi++)
                #pragma unroll
                for (int ni = 0; ni < 4; ni++)
                    mma_bf16(acc[mi][ni], ah[mi], bl[ni]);     // hi * lo
            #pragma unroll
            for (int mi = 0; mi < 4; mi++)
                ldsm_x4(ah[mi], (st + ST_AL + aswz + mi * 1024) ^ ko);
            #pragma unroll
            for (int mi = 0; mi < 4; mi++)
                #pragma unroll
                for (int ni = 0; ni < 4; ni++)
                    mma_bf16(acc[mi][ni], ah[mi], bh[ni]);     // lo * hi
        }
    }
}

// --------------------------- conversion kernels -----------------------------
__global__ __launch_bounds__(256) void convert_x(const float* __restrict__ x) {
    size_t i = ((size_t)blockIdx.x * 256 + threadIdx.x) * 4;
    float4 v = *(const float4*)(x + i);
    __nv_bfloat16 h[4], l[4];
    float vv[4] = {v.x, v.y, v.z, v.w};
    #pragma unroll
    for (int j = 0; j < 4; j++) {
        h[j] = __float2bfloat16(vv[j]);
        l[j] = __float2bfloat16(vv[j] - __bfloat162float(h[j]));
    }
    *(__nv_bfloat162*)(Xhi + i)     = __nv_bfloat162(h[0], h[1]);
    *(__nv_bfloat162*)(Xhi + i + 2) = __nv_bfloat162(h[2], h[3]);
    *(__nv_bfloat162*)(Xlo + i)     = __nv_bfloat162(l[0], l[1]);
    *(__nv_bfloat162*)(Xlo + i + 2) = __nv_bfloat162(l[2], l[3]);
}

__global__ void convert_w(const float* __restrict__ Wq,
                          const float* __restrict__ Wk,
                          const float* __restrict__ Wv) {
    __shared__ float t[32][33];
    const int z = blockIdx.z;
    const float* W = (z == 0) ? Wq : ((z == 1) ? Wk : Wv);
    const int n0 = blockIdx.x * 32, k0 = blockIdx.y * 32;
    const int tx = threadIdx.x, ty = threadIdx.y;
    #pragma unroll
    for (int r = ty; r < 32; r += 8)
        t[r][tx] = W[(size_t)(k0 + r) * DIM + n0 + tx];
    __syncthreads();
    __nv_bfloat16* oh = Wthi + (size_t)z * DIM * DIM;
    __nv_bfloat16* ol = Wtlo + (size_t)z * DIM * DIM;
    #pragma unroll
    for (int r = ty; r < 32; r += 8) {
        float v = t[tx][r];
        __nv_bfloat16 h = __float2bfloat16(v);
        oh[(size_t)(n0 + r) * DIM + k0 + tx] = h;
        ol[(size_t)(n0 + r) * DIM + k0 + tx] = __float2bfloat16(v - __bfloat162float(h));
    }
}

// V transpose (hi/lo): Vt[b][d][s] = V[b][s][d]
__global__ void transpose_v() {
    __shared__ __nv_bfloat16 th[32][33], tl[32][33];
    const int b = blockIdx.z;
    const int d0 = blockIdx.x * 32, s0 = blockIdx.y * 32;
    const int tx = threadIdx.x, ty = threadIdx.y;
    const __nv_bfloat16* vh = Vhi + (size_t)b * SEQ * DIM;
    const __nv_bfloat16* vl = Vlo + (size_t)b * SEQ * DIM;
    #pragma unroll
    for (int r = ty; r < 32; r += 8) {
        th[r][tx] = vh[(size_t)(s0 + r) * DIM + d0 + tx];
        tl[r][tx] = vl[(size_t)(s0 + r) * DIM + d0 + tx];
    }
    __syncthreads();
    __nv_bfloat16* oh = Vthi + (size_t)b * DIM * SEQ;
    __nv_bfloat16* ol = Vtlo + (size_t)b * DIM * SEQ;
    #pragma unroll
    for (int r = ty; r < 32; r += 8) {
        oh[(size_t)(d0 + r) * SEQ + s0 + tx] = th[tx][r];
        ol[(size_t)(d0 + r) * SEQ + s0 + tx] = tl[tx][r];
    }
}

// ---------------- QKV GEMM: writes Q/K/V as bf16 hi/lo ----------------------
__global__ __launch_bounds__(256) void qkv_gemm_mma() {
    extern __shared__ char smg[];
    const int tid = threadIdx.x;
    const int wid = tid >> 5, lane = tid & 31;
    const int n0 = blockIdx.x * 128, m0 = blockIdx.y * 128, z = blockIdx.z;
    const int wm = (wid & 1) * 64, wn = (wid >> 1) * 32;

    float acc[4][4][4] = {};
    gemm_tile_db(Xhi + (size_t)m0 * DIM, Xlo + (size_t)m0 * DIM, DIM,
                 Wthi + (size_t)z * DIM * DIM + (size_t)n0 * DIM,
                 Wtlo + (size_t)z * DIM * DIM + (size_t)n0 * DIM, DIM,
                 DIM / 32, smg, acc);

    __nv_bfloat16* Dh = (z == 0) ? Qhi : ((z == 1) ? Khi : Vhi);
    __nv_bfloat16* Dl = (z == 0) ? Qlo : ((z == 1) ? Klo : Vlo);

    #pragma unroll
    for (int mi = 0; mi < 4; mi++) {
        const int row0 = m0 + wm + mi * 16 + (lane >> 2);
        #pragma unroll
        for (int ni = 0; ni < 4; ni++) {
            const int col = n0 + wn + ni * 8 + (lane & 3) * 2;
            #pragma unroll
            for (int half = 0; half < 2; half++) {
                const float v0 = acc[mi][ni][half * 2 + 0];
                const float v1 = acc[mi][ni][half * 2 + 1];
                const __nv_bfloat16 h0 = __float2bfloat16(v0);
                const __nv_bfloat16 h1 = __float2bfloat16(v1);
                const size_t idx = (size_t)(row0 + half * 8) * DIM + col;
                *(__nv_bfloat162*)(Dh + idx) = __nv_bfloat162(h0, h1);
                *(__nv_bfloat162*)(Dl + idx) = __nv_bfloat162(
                    __float2bfloat16(v0 - __bfloat162float(h0)),
                    __float2bfloat16(v1 - __bfloat162float(h1)));
            }
        }
    }
}

// ---------------- S GEMM: Sg = Q @ K^T (triangular tiles, unscaled) ---------
__global__ __launch_bounds__(256) void s_gemm() {
    const int bn = blockIdx.x;
    const int bm = gridDim.y - 1 - blockIdx.y;   // heavy tiles first
    const int b  = blockIdx.z;
    if (bn > bm) return;                         // tile fully above diagonal
    extern __shared__ char smg[];
    const int tid = threadIdx.x;
    const int wid = tid >> 5, lane = tid & 31;
    const int m0 = bm * 128, n0 = bn * 128;
    const int wm = (wid & 1) * 64, wn = (wid >> 1) * 32;

    const size_t boff = (size_t)b * SEQ * DIM;
    float acc[4][4][4] = {};
    gemm_tile_db(Qhi + boff + (size_t)m0 * DIM, Qlo + boff + (size_t)m0 * DIM, DIM,
                 Khi + boff + (size_t)n0 * DIM, Klo + boff + (size_t)n0 * DIM, DIM,
                 DIM / 32, smg, acc);

    float* S = Sg + (size_t)b * SEQ * SEQ;
    #pragma unroll
    for (int mi = 0; mi < 4; mi++) {
        const int row0 = m0 + wm + mi * 16 + (lane >> 2);
        #pragma unroll
        for (int ni = 0; ni < 4; ni++) {
            const int col = n0 + wn + ni * 8 + (lane & 3) * 2;
            *(float2*)(S + (size_t)row0 * SEQ + col) =
                make_float2(acc[mi][ni][0], acc[mi][ni][1]);
            *(float2*)(S + (size_t)(row0 + 8) * SEQ + col) =
                make_float2(acc[mi][ni][2], acc[mi][ni][3]);
        }
    }
}

// ---------------- softmax + hi/lo split: Sg -> Phi/Plo -----------------------
__global__ __launch_bounds__(256) void softmax_split() {
    __shared__ float ebuf[SEQ];
    __shared__ float red[8];
    const int q = blockIdx.x, b = blockIdx.y;
    const int n = q + 1;
    const int rowpad = ((q >> 7) << 7) + 128;
    const int tid = threadIdx.x, wid = tid >> 5, lane = tid & 31;
    const float scale = 0.03125f;

    const float* srow = Sg + ((size_t)b * SEQ + q) * SEQ;

    float mx = -1e30f;
    for (int i = tid; i < n; i += 256) mx = fmaxf(mx, srow[i] * scale);
    #pragma unroll
    for (int o = 16; o; o >>= 1) mx = fmaxf(mx, __shfl_xor_sync(0xffffffffu, mx, o));
    if (lane == 0) red[wid] = mx;
    __syncthreads();
    float m2 = red[0];
    #pragma unroll
    for (int i = 1; i < 8; i++) m2 = fmaxf(m2, red[i]);
    __syncthreads();

    float sum = 0.0f;
    for (int i = tid; i < n; i += 256) {
        float e = __expf(srow[i] * scale - m2);
        ebuf[i] = e;
        sum += e;
    }
    #pragma unroll
    for (int o = 16; o; o >>= 1) sum += __shfl_xor_sync(0xffffffffu, sum, o);
    if (lane == 0) red[wid] = sum;
    __syncthreads();
    float s2 = red[0];
    #pragma unroll
    for (int i = 1; i < 8; i++) s2 += red[i];
    const float inv = 1.0f / s2;

    __nv_bfloat16* ph = Phi + ((size_t)b * SEQ + q) * SEQ;
    __nv_bfloat16* pl = Plo + ((size_t)b * SEQ + q) * SEQ;
    for (int i = tid; i < rowpad; i += 256) {
        const float p = (i < n) ? ebuf[i] * inv : 0.0f;
        const __nv_bfloat16 h = __float2bfloat16(p);
        ph[i] = h;
        pl[i] = __float2bfloat16(p - __bfloat162float(h));
    }
}

// ---------------- O GEMM: out = P @ V (causal k-range) ----------------------
__global__ __launch_bounds__(256) void o_gemm(float* __restrict__ out) {
    extern __shared__ char smg[];
    const int tid = threadIdx.x;
    const int wid = tid >> 5, lane = tid & 31;
    const int bn = blockIdx.x;
    const int bm = gridDim.y - 1 - blockIdx.y;   // heavy rows first
    const int b  = blockIdx.z;
    const int m0 = bm * 128, n0 = bn * 128;
    const int wm = (wid & 1) * 64, wn = (wid >> 1) * 32;

    const size_t poff = (size_t)b * SEQ * SEQ;
    const size_t voff = (size_t)b * DIM * SEQ;
    float acc[4][4][4] = {};
    gemm_tile_db(Phi + poff + (size_t)m0 * SEQ, Plo + poff + (size_t)m0 * SEQ, SEQ,
                 Vthi + voff + (size_t)n0 * SEQ, Vtlo + voff + (size_t)n0 * SEQ, SEQ,
                 (m0 + 128) / 32, smg, acc);

    float* O = out + (size_t)b * SEQ * DIM;
    #pragma unroll
    for (int mi = 0; mi < 4; mi++) {
        const int row0 = m0 + wm + mi * 16 + (lane >> 2);
        #pragma unroll
        for (int ni = 0; ni < 4; ni++) {
            const int col = n0 + wn + ni * 8 + (lane & 3) * 2;
            *(float2*)(O + (size_t)row0 * DIM + col) =
                make_float2(acc[mi][ni][0], acc[mi][ni][1]);
            *(float2*)(O + (size_t)(row0 + 8) * DIM + col) =
                make_float2(acc[mi][ni][2], acc[mi][ni][3]);
        }
    }
}

// ---------------------------------------------------------------------------
extern "C" void kernel_launch(void* const* d_in, const int* in_sizes, int n_in,
                              void* d_out, int out_size)
{
    const float* x  = (const float*)d_in[0];
    const float* Wq = (const float*)d_in[1];
    const float* Wk = (const float*)d_in[2];
    const float* Wv = (const float*)d_in[3];
    float* out = (float*)d_out;

    cudaFuncSetAttribute(qkv_gemm_mma, cudaFuncAttributeMaxDynamicSharedMemorySize, GEMM_SMEM);
    cudaFuncSetAttribute(s_gemm,       cudaFuncAttributeMaxDynamicSharedMemorySize, GEMM_SMEM);
    cudaFuncSetAttribute(o_gemm,       cudaFuncAttributeMaxDynamicSharedMemorySize, GEMM_SMEM);

    // fp32 -> bf16 hi/lo
    convert_x<<<MTOT * DIM / (256 * 4), 256>>>(x);
    convert_w<<<dim3(DIM / 32, DIM / 32, 3), dim3(32, 8)>>>(Wq, Wk, Wv);

    // QKV projections (HMMA bf16x3, 4-stage cp.async, 128x128 tiles)
    qkv_gemm_mma<<<dim3(DIM / 128, MTOT / 128, 3), 256, GEMM_SMEM>>>();

    // V transpose for the PV GEMM
    transpose_v<<<dim3(DIM / 32, SEQ / 32, BATCH), dim3(32, 8)>>>();

    // Scores (triangular), softmax, PV
    s_gemm<<<dim3(SEQ / 128, SEQ / 128, BATCH), 256, GEMM_SMEM>>>();
    softmax_split<<<dim3(SEQ, BATCH), 256>>>();
    o_gemm<<<dim3(DIM / 128, SEQ / 128, BATCH), 256, GEMM_SMEM>>>(out);
}

// round 7
// speedup vs baseline: 1.1547x; 1.1547x over previous
#include <cuda_runtime.h>
#include <cuda_bf16.h>
#include <cstdint>

#define BATCH 4
#define SEQ   2048
#define DIM   1024
#define MTOT  (BATCH*SEQ)

// ------------------------- device scratch (no allocs) -----------------------
__device__ __nv_bfloat16 Xhi[MTOT*(size_t)DIM];
__device__ __nv_bfloat16 Xlo[MTOT*(size_t)DIM];
__device__ __nv_bfloat16 Wthi[3*(size_t)DIM*DIM];   // [z][n][k]
__device__ __nv_bfloat16 Wtlo[3*(size_t)DIM*DIM];
__device__ __nv_bfloat16 Qhi[MTOT*(size_t)DIM];
__device__ __nv_bfloat16 Qlo[MTOT*(size_t)DIM];
__device__ __nv_bfloat16 Khi[MTOT*(size_t)DIM];
__device__ __nv_bfloat16 Klo[MTOT*(size_t)DIM];
__device__ __nv_bfloat16 Vhi[MTOT*(size_t)DIM];
__device__ __nv_bfloat16 Vlo[MTOT*(size_t)DIM];
__device__ __nv_bfloat16 Vthi[MTOT*(size_t)DIM];    // [b][d][s]
__device__ __nv_bfloat16 Vtlo[MTOT*(size_t)DIM];
__device__ float         Sg  [(size_t)BATCH*SEQ*SEQ];   // [b][q][k]
__device__ __nv_bfloat16 Phi [(size_t)BATCH*SEQ*SEQ];
__device__ __nv_bfloat16 Plo [(size_t)BATCH*SEQ*SEQ];

// ------------------------------ helpers -------------------------------------
__device__ __forceinline__ uint32_t smem_to_u32(const void* p) {
    uint32_t a;
    asm("{ .reg .u64 t; cvta.to.shared.u64 t, %1; cvt.u32.u64 %0, t; }"
        : "=r"(a) : "l"(p));
    return a;
}
// 64B-row swizzle: bits[5:4] ^= bits[8:7]  (proven correct in R6)
#define SW64(off) ((off) ^ (((off) >> 3) & 0x30))

__device__ __forceinline__ void ldsm_x4(uint32_t* r, uint32_t addr) {
    asm volatile("ldmatrix.sync.aligned.m8n8.x4.shared.b16 {%0,%1,%2,%3}, [%4];"
                 : "=r"(r[0]), "=r"(r[1]), "=r"(r[2]), "=r"(r[3]) : "r"(addr));
}
__device__ __forceinline__ void mma_bf16(float* c, const uint32_t* a, const uint32_t* b) {
    asm volatile(
        "mma.sync.aligned.m16n8k16.row.col.f32.bf16.bf16.f32 "
        "{%0,%1,%2,%3}, {%4,%5,%6,%7}, {%8,%9}, {%0,%1,%2,%3};"
        : "+f"(c[0]), "+f"(c[1]), "+f"(c[2]), "+f"(c[3])
        : "r"(a[0]), "r"(a[1]), "r"(a[2]), "r"(a[3]), "r"(b[0]), "r"(b[1]));
}
__device__ __forceinline__ void cp16(uint32_t smem_dst, const void* gptr) {
    asm volatile("cp.async.cg.shared.global [%0], [%1], 16;"
                 :: "r"(smem_dst), "l"(gptr));
}

// ----------------- 4-stage bf16x3 mainloop -----------------------------------
// Block tile 128m x 64n x 32k. 8 warps: 4(m) x 2(n), warp tile 32x32.
// Stage (24 KB): Ah[8K] Al[8K] Bh[4K] Bl[4K]; rows are 64B, SW64 swizzled.
// 4 stages = 96 KB -> 2 CTAs/SM. Single barrier per chunk (issue-ahead 3).
#define ST_AH 0
#define ST_AL 8192
#define ST_BH 16384
#define ST_BL 20480
#define STAGE 24576
#define NSTAGE 4
#define GEMM_SMEM (NSTAGE*STAGE)   // 98304

__device__ __forceinline__ void gemm_tile_db(
    const __nv_bfloat16* __restrict__ Ah, const __nv_bfloat16* __restrict__ Al, int lda,
    const __nv_bfloat16* __restrict__ Bh, const __nv_bfloat16* __restrict__ Bl, int ldb,
    int kIters, char* smem, float acc[2][4][4])
{
    const int tid = threadIdx.x;
    const int wid = tid >> 5, lane = tid & 31;
    const int wm = (wid & 3) * 32;     // warp m offset
    const int wn = (wid >> 2) * 32;    // warp n offset
    const uint32_t sbase = smem_to_u32(smem);

    // cp.async geometry: thread covers A rows r0, r0+64 and B row r0; 16B chunk c4
    const int r0 = tid >> 2, c4 = tid & 3;
    const uint32_t so0 = SW64((uint32_t)(r0 * 64 + c4 * 16));
    const size_t gA0 = (size_t)r0 * lda + c4 * 8;
    const size_t gA1 = gA0 + (size_t)64 * lda;
    const size_t gB0 = (size_t)r0 * ldb + c4 * 8;

    auto issue = [&](int c) {
        const uint32_t st = sbase + (uint32_t)(c & (NSTAGE - 1)) * STAGE;
        const int kc = c * 32;
        cp16(st + ST_AH + so0,        Ah + gA0 + kc);
        cp16(st + ST_AH + so0 + 4096, Ah + gA1 + kc);
        cp16(st + ST_AL + so0,        Al + gA0 + kc);
        cp16(st + ST_AL + so0 + 4096, Al + gA1 + kc);
        cp16(st + ST_BH + so0,        Bh + gB0 + kc);
        cp16(st + ST_BL + so0,        Bl + gB0 + kc);
        asm volatile("cp.async.commit_group;" ::: "memory");
    };

    // ldmatrix swizzled per-thread bases. Row bits feeding the swizzle (byte
    // bits 7,8) come only from lane bits, so wm/wn/mi/p offsets (multiples of
    // 1024B) compose additively; the k-step (byte bit 5) composes by XOR.
    const uint32_t aswz = SW64((uint32_t)((lane & 15) * 64 + ((lane >> 4) & 1) * 16))
                          + (uint32_t)wm * 64;
    const uint32_t bswz = SW64((uint32_t)((((lane & 7) + ((lane >> 4) & 1) * 8)) * 64
                                          + ((lane >> 3) & 1) * 16))
                          + (uint32_t)wn * 64;

    issue(0);
    if (kIters > 1) issue(1);
    if (kIters > 2) issue(2);

    for (int c = 0; c < kIters; c++) {
        const int rem = kIters - 1 - c;
        if (rem >= 2)      asm volatile("cp.async.wait_group 2;" ::: "memory");
        else if (rem == 1) asm volatile("cp.async.wait_group 1;" ::: "memory");
        else               asm volatile("cp.async.wait_group 0;" ::: "memory");
        __syncthreads();
        if (c + 3 < kIters) issue(c + 3);

        const uint32_t st = sbase + (uint32_t)(c & (NSTAGE - 1)) * STAGE;
        #pragma unroll
        for (int ks = 0; ks < 2; ks++) {
            const uint32_t ko = (uint32_t)ks * 32;
            uint32_t ah[2][4], al[2][4], bh[4][2], bl[4][2], t[4];
            #pragma unroll
            for (int mi = 0; mi < 2; mi++) {
                ldsm_x4(ah[mi], (st + ST_AH + aswz + mi * 1024) ^ ko);
                ldsm_x4(al[mi], (st + ST_AL + aswz + mi * 1024) ^ ko);
            }
            #pragma unroll
            for (int p = 0; p < 2; p++) {
                ldsm_x4(t, (st + ST_BH + bswz + p * 1024) ^ ko);
                bh[2*p][0] = t[0]; bh[2*p][1] = t[1];
                bh[2*p+1][0] = t[2]; bh[2*p+1][1] = t[3];
                ldsm_x4(t, (st + ST_BL + bswz + p * 1024) ^ ko);
                bl[2*p][0] = t[0]; bl[2*p][1] = t[1];
                bl[2*p+1][0] = t[2]; bl[2*p+1][1] = t[3];
            }
            #pragma unroll
            for (int mi = 0; mi < 2; mi++)
                #pragma unroll
                for (int ni = 0; ni < 4; ni++) {
                    mma_bf16(acc[mi][ni], ah[mi], bh[ni]);
                    mma_bf16(acc[mi][ni], ah[mi], bl[ni]);
                    mma_bf16(acc[mi][ni], al[mi], bh[ni]);
                }
        }
    }
}

// --------------------------- conversion kernels -----------------------------
__global__ __launch_bounds__(256) void convert_x(const float* __restrict__ x) {
    size_t i = ((size_t)blockIdx.x * 256 + threadIdx.x) * 4;
    float4 v = *(const float4*)(x + i);
    __nv_bfloat16 h[4], l[4];
    float vv[4] = {v.x, v.y, v.z, v.w};
    #pragma unroll
    for (int j = 0; j < 4; j++) {
        h[j] = __float2bfloat16(vv[j]);
        l[j] = __float2bfloat16(vv[j] - __bfloat162float(h[j]));
    }
    *(__nv_bfloat162*)(Xhi + i)     = __nv_bfloat162(h[0], h[1]);
    *(__nv_bfloat162*)(Xhi + i + 2) = __nv_bfloat162(h[2], h[3]);
    *(__nv_bfloat162*)(Xlo + i)     = __nv_bfloat162(l[0], l[1]);
    *(__nv_bfloat162*)(Xlo + i + 2) = __nv_bfloat162(l[2], l[3]);
}

__global__ void convert_w(const float* __restrict__ Wq,
                          const float* __restrict__ Wk,
                          const float* __restrict__ Wv) {
    __shared__ float t[32][33];
    const int z = blockIdx.z;
    const float* W = (z == 0) ? Wq : ((z == 1) ? Wk : Wv);
    const int n0 = blockIdx.x * 32, k0 = blockIdx.y * 32;
    const int tx = threadIdx.x, ty = threadIdx.y;
    #pragma unroll
    for (int r = ty; r < 32; r += 8)
        t[r][tx] = W[(size_t)(k0 + r) * DIM + n0 + tx];
    __syncthreads();
    __nv_bfloat16* oh = Wthi + (size_t)z * DIM * DIM;
    __nv_bfloat16* ol = Wtlo + (size_t)z * DIM * DIM;
    #pragma unroll
    for (int r = ty; r < 32; r += 8) {
        float v = t[tx][r];
        __nv_bfloat16 h = __float2bfloat16(v);
        oh[(size_t)(n0 + r) * DIM + k0 + tx] = h;
        ol[(size_t)(n0 + r) * DIM + k0 + tx] = __float2bfloat16(v - __bfloat162float(h));
    }
}

// V transpose (hi/lo): Vt[b][d][s] = V[b][s][d]
__global__ void transpose_v() {
    __shared__ __nv_bfloat16 th[32][33], tl[32][33];
    const int b = blockIdx.z;
    const int d0 = blockIdx.x * 32, s0 = blockIdx.y * 32;
    const int tx = threadIdx.x, ty = threadIdx.y;
    const __nv_bfloat16* vh = Vhi + (size_t)b * SEQ * DIM;
    const __nv_bfloat16* vl = Vlo + (size_t)b * SEQ * DIM;
    #pragma unroll
    for (int r = ty; r < 32; r += 8) {
        th[r][tx] = vh[(size_t)(s0 + r) * DIM + d0 + tx];
        tl[r][tx] = vl[(size_t)(s0 + r) * DIM + d0 + tx];
    }
    __syncthreads();
    __nv_bfloat16* oh = Vthi + (size_t)b * DIM * SEQ;
    __nv_bfloat16* ol = Vtlo + (size_t)b * DIM * SEQ;
    #pragma unroll
    for (int r = ty; r < 32; r += 8) {
        oh[(size_t)(d0 + r) * SEQ + s0 + tx] = th[tx][r];
        ol[(size_t)(d0 + r) * SEQ + s0 + tx] = tl[tx][r];
    }
}

// ---------------- QKV GEMM: writes Q/K/V as bf16 hi/lo ----------------------
__global__ __launch_bounds__(256, 2) void qkv_gemm_mma() {
    extern __shared__ char smg[];
    const int tid = threadIdx.x;
    const int wid = tid >> 5, lane = tid & 31;
    const int n0 = blockIdx.x * 64, m0 = blockIdx.y * 128, z = blockIdx.z;
    const int wm = (wid & 3) * 32, wn = (wid >> 2) * 32;

    float acc[2][4][4] = {};
    gemm_tile_db(Xhi + (size_t)m0 * DIM, Xlo + (size_t)m0 * DIM, DIM,
                 Wthi + (size_t)z * DIM * DIM + (size_t)n0 * DIM,
                 Wtlo + (size_t)z * DIM * DIM + (size_t)n0 * DIM, DIM,
                 DIM / 32, smg, acc);

    __nv_bfloat16* Dh = (z == 0) ? Qhi : ((z == 1) ? Khi : Vhi);
    __nv_bfloat16* Dl = (z == 0) ? Qlo : ((z == 1) ? Klo : Vlo);

    #pragma unroll
    for (int mi = 0; mi < 2; mi++) {
        const int row0 = m0 + wm + mi * 16 + (lane >> 2);
        #pragma unroll
        for (int ni = 0; ni < 4; ni++) {
            const int col = n0 + wn + ni * 8 + (lane & 3) * 2;
            #pragma unroll
            for (int half = 0; half < 2; half++) {
                const float v0 = acc[mi][ni][half * 2 + 0];
                const float v1 = acc[mi][ni][half * 2 + 1];
                const __nv_bfloat16 h0 = __float2bfloat16(v0);
                const __nv_bfloat16 h1 = __float2bfloat16(v1);
                const size_t idx = (size_t)(row0 + half * 8) * DIM + col;
                *(__nv_bfloat162*)(Dh + idx) = __nv_bfloat162(h0, h1);
                *(__nv_bfloat162*)(Dl + idx) = __nv_bfloat162(
                    __float2bfloat16(v0 - __bfloat162float(h0)),
                    __float2bfloat16(v1 - __bfloat162float(h1)));
            }
        }
    }
}

// ---------------- S GEMM: Sg = Q @ K^T (triangular tiles, unscaled) ---------
__global__ __launch_bounds__(256, 2) void s_gemm() {
    const int bn = blockIdx.x;
    const int bm = gridDim.y - 1 - blockIdx.y;   // heavy tiles first
    const int b  = blockIdx.z;
    if (bn > 2 * bm + 1) return;                 // tile fully above diagonal
    extern __shared__ char smg[];
    const int tid = threadIdx.x;
    const int wid = tid >> 5, lane = tid & 31;
    const int m0 = bm * 128, n0 = bn * 64;
    const int wm = (wid & 3) * 32, wn = (wid >> 2) * 32;

    const size_t boff = (size_t)b * SEQ * DIM;
    float acc[2][4][4] = {};
    gemm_tile_db(Qhi + boff + (size_t)m0 * DIM, Qlo + boff + (size_t)m0 * DIM, DIM,
                 Khi + boff + (size_t)n0 * DIM, Klo + boff + (size_t)n0 * DIM, DIM,
                 DIM / 32, smg, acc);

    float* S = Sg + (size_t)b * SEQ * SEQ;
    #pragma unroll
    for (int mi = 0; mi < 2; mi++) {
        const int row0 = m0 + wm + mi * 16 + (lane >> 2);
        #pragma unroll
        for (int ni = 0; ni < 4; ni++) {
            const int col = n0 + wn + ni * 8 + (lane & 3) * 2;
            *(float2*)(S + (size_t)row0 * SEQ + col) =
                make_float2(acc[mi][ni][0], acc[mi][ni][1]);
            *(float2*)(S + (size_t)(row0 + 8) * SEQ + col) =
                make_float2(acc[mi][ni][2], acc[mi][ni][3]);
        }
    }
}

// ---------------- softmax + hi/lo split: Sg -> Phi/Plo -----------------------
__global__ __launch_bounds__(256) void softmax_split() {
    __shared__ float ebuf[SEQ];
    __shared__ float red[8];
    const int q = blockIdx.x, b = blockIdx.y;
    const int n = q + 1;
    const int rowpad = ((q >> 7) << 7) + 128;
    const int tid = threadIdx.x, wid = tid >> 5, lane = tid & 31;
    const float scale = 0.03125f;

    const float* srow = Sg + ((size_t)b * SEQ + q) * SEQ;

    float mx = -1e30f;
    for (int i = tid; i < n; i += 256) mx = fmaxf(mx, srow[i] * scale);
    #pragma unroll
    for (int o = 16; o; o >>= 1) mx = fmaxf(mx, __shfl_xor_sync(0xffffffffu, mx, o));
    if (lane == 0) red[wid] = mx;
    __syncthreads();
    float m2 = red[0];
    #pragma unroll
    for (int i = 1; i < 8; i++) m2 = fmaxf(m2, red[i]);
    __syncthreads();

    float sum = 0.0f;
    for (int i = tid; i < n; i += 256) {
        float e = __expf(srow[i] * scale - m2);
        ebuf[i] = e;
        sum += e;
    }
    #pragma unroll
    for (int o = 16; o; o >>= 1) sum += __shfl_xor_sync(0xffffffffu, sum, o);
    if (lane == 0) red[wid] = sum;
    __syncthreads();
    float s2 = red[0];
    #pragma unroll
    for (int i = 1; i < 8; i++) s2 += red[i];
    const float inv = 1.0f / s2;

    __nv_bfloat16* ph = Phi + ((size_t)b * SEQ + q) * SEQ;
    __nv_bfloat16* pl = Plo + ((size_t)b * SEQ + q) * SEQ;
    for (int i = tid; i < rowpad; i += 256) {
        const float p = (i < n) ? ebuf[i] * inv : 0.0f;
        const __nv_bfloat16 h = __float2bfloat16(p);
        ph[i] = h;
        pl[i] = __float2bfloat16(p - __bfloat162float(h));
    }
}

// ---------------- O GEMM: out = P @ V (causal k-range) ----------------------
__global__ __launch_bounds__(256, 2) void o_gemm(float* __restrict__ out) {
    extern __shared__ char smg[];
    const int tid = threadIdx.x;
    const int wid = tid >> 5, lane = tid & 31;
    const int bn = blockIdx.x;
    const int bm = gridDim.y - 1 - blockIdx.y;   // heavy rows first
    const int b  = blockIdx.z;
    const int m0 = bm * 128, n0 = bn * 64;
    const int wm = (wid & 3) * 32, wn = (wid >> 2) * 32;

    const size_t poff = (size_t)b * SEQ * SEQ;
    const size_t voff = (size_t)b * DIM * SEQ;
    float acc[2][4][4] = {};
    gemm_tile_db(Phi + poff + (size_t)m0 * SEQ, Plo + poff + (size_t)m0 * SEQ, SEQ,
                 Vthi + voff + (size_t)n0 * SEQ, Vtlo + voff + (size_t)n0 * SEQ, SEQ,
                 (m0 + 128) / 32, smg, acc);

    float* O = out + (size_t)b * SEQ * DIM;
    #pragma unroll
    for (int mi = 0; mi < 2; mi++) {
        const int row0 = m0 + wm + mi * 16 + (lane >> 2);
        #pragma unroll
        for (int ni = 0; ni < 4; ni++) {
            const int col = n0 + wn + ni * 8 + (lane & 3) * 2;
            *(float2*)(O + (size_t)row0 * DIM + col) =
                make_float2(acc[mi][ni][0], acc[mi][ni][1]);
            *(float2*)(O + (size_t)(row0 + 8) * DIM + col) =
                make_float2(acc[mi][ni][2], acc[mi][ni][3]);
        }
    }
}

// ---------------------------------------------------------------------------
extern "C" void kernel_launch(void* const* d_in, const int* in_sizes, int n_in,
                              void* d_out, int out_size)
{
    const float* x  = (const float*)d_in[0];
    const float* Wq = (const float*)d_in[1];
    const float* Wk = (const float*)d_in[2];
    const float* Wv = (const float*)d_in[3];
    float* out = (float*)d_out;

    cudaFuncSetAttribute(qkv_gemm_mma, cudaFuncAttributeMaxDynamicSharedMemorySize, GEMM_SMEM);
    cudaFuncSetAttribute(s_gemm,       cudaFuncAttributeMaxDynamicSharedMemorySize, GEMM_SMEM);
    cudaFuncSetAttribute(o_gemm,       cudaFuncAttributeMaxDynamicSharedMemorySize, GEMM_SMEM);

    // fp32 -> bf16 hi/lo
    convert_x<<<MTOT * DIM / (256 * 4), 256>>>(x);
    convert_w<<<dim3(DIM / 32, DIM / 32, 3), dim3(32, 8)>>>(Wq, Wk, Wv);

    // QKV projections (HMMA bf16x3, 4-stage cp.async, 128x64 tiles)
    qkv_gemm_mma<<<dim3(DIM / 64, MTOT / 128, 3), 256, GEMM_SMEM>>>();

    // V transpose for the PV GEMM
    transpose_v<<<dim3(DIM / 32, SEQ / 32, BATCH), dim3(32, 8)>>>();

    // Scores (triangular), softmax, PV
    s_gemm<<<dim3(SEQ / 64, SEQ / 128, BATCH), 256, GEMM_SMEM>>>();
    softmax_split<<<dim3(SEQ, BATCH), 256>>>();
    o_gemm<<<dim3(DIM / 64, SEQ / 128, BATCH), 256, GEMM_SMEM>>>(out);
}

// round 8
// speedup vs baseline: 1.2805x; 1.1090x over previous
#include <cuda_runtime.h>
#include <cuda_bf16.h>
#include <cstdint>

#define BATCH 4
#define SEQ   2048
#define DIM   1024
#define MTOT  (BATCH*SEQ)

// ------------------------- device scratch (no allocs) -----------------------
__device__ __nv_bfloat16 Xhi[MTOT*(size_t)DIM];
__device__ __nv_bfloat16 Xlo[MTOT*(size_t)DIM];
__device__ __nv_bfloat16 Wthi[3*(size_t)DIM*DIM];   // [z][n][k]
__device__ __nv_bfloat16 Wtlo[3*(size_t)DIM*DIM];
__device__ __nv_bfloat16 Qhi[MTOT*(size_t)DIM];
__device__ __nv_bfloat16 Qlo[MTOT*(size_t)DIM];
__device__ __nv_bfloat16 Khi[MTOT*(size_t)DIM];
__device__ __nv_bfloat16 Klo[MTOT*(size_t)DIM];
__device__ __nv_bfloat16 Vthi[MTOT*(size_t)DIM];    // [b][d][s]
__device__ __nv_bfloat16 Vtlo[MTOT*(size_t)DIM];
__device__ float         Sg  [(size_t)BATCH*SEQ*SEQ];   // [b][q][k]
__device__ __nv_bfloat16 Phi [(size_t)BATCH*SEQ*SEQ];
__device__ __nv_bfloat16 Plo [(size_t)BATCH*SEQ*SEQ];

// ------------------------------ helpers -------------------------------------
__device__ __forceinline__ uint32_t smem_to_u32(const void* p) {
    uint32_t a;
    asm("{ .reg .u64 t; cvta.to.shared.u64 t, %1; cvt.u32.u64 %0, t; }"
        : "=r"(a) : "l"(p));
    return a;
}
#define SW128(off) ((off) ^ (((off) >> 3) & 0x70))

__device__ __forceinline__ void ldsm_x4(uint32_t* r, uint32_t addr) {
    asm volatile("ldmatrix.sync.aligned.m8n8.x4.shared.b16 {%0,%1,%2,%3}, [%4];"
                 : "=r"(r[0]), "=r"(r[1]), "=r"(r[2]), "=r"(r[3]) : "r"(addr));
}
__device__ __forceinline__ void mma_bf16(float* c, const uint32_t* a, const uint32_t* b) {
    asm volatile(
        "mma.sync.aligned.m16n8k16.row.col.f32.bf16.bf16.f32 "
        "{%0,%1,%2,%3}, {%4,%5,%6,%7}, {%8,%9}, {%0,%1,%2,%3};"
        : "+f"(c[0]), "+f"(c[1]), "+f"(c[2]), "+f"(c[3])
        : "r"(a[0]), "r"(a[1]), "r"(a[2]), "r"(a[3]), "r"(b[0]), "r"(b[1]));
}
__device__ __forceinline__ void cp16(uint32_t smem_dst, const void* gptr) {
    asm volatile("cp.async.cg.shared.global [%0], [%1], 16;"
                 :: "r"(smem_dst), "l"(gptr));
}

// ----------------- double-buffered bf16x3 mainloop (R5, proven) --------------
// Block tile 128m x 64n x 64k, 8 warps (warp tile 32x32), cp.async 2-stage.
// Stage layout (48 KB): Ah[16K] Al[16K] Bh[8K] Bl[8K].
#define ST_AH 0
#define ST_AL 16384
#define ST_BH 32768
#define ST_BL 40960
#define STAGE 49152
#define GEMM_SMEM (2*STAGE)   // 98304

__device__ __forceinline__ void gemm_tile_db(
    const __nv_bfloat16* __restrict__ Ah, const __nv_bfloat16* __restrict__ Al, size_t lda,
    const __nv_bfloat16* __restrict__ Bh, const __nv_bfloat16* __restrict__ Bl, size_t ldb,
    int kIters, char* smem, float acc[2][4][4])
{
    const int tid = threadIdx.x;
    const int wid = tid >> 5, lane = tid & 31;
    const int wm = (wid & 3) * 32;
    const int wn = (wid >> 2) * 32;
    const uint32_t sbase = smem_to_u32(smem);

    const int r8 = tid >> 3, j8 = tid & 7;

    auto issue = [&](int c) {
        const int kc = c * 64;
        const uint32_t st = sbase + (c & 1) * STAGE;
        #pragma unroll
        for (int i = 0; i < 4; i++) {
            const int r = r8 + i * 32;
            const uint32_t off = SW128((uint32_t)(r * 128 + j8 * 16));
            const size_t g = (size_t)r * lda + kc + j8 * 8;
            cp16(st + ST_AH + off, Ah + g);
            cp16(st + ST_AL + off, Al + g);
        }
        #pragma unroll
        for (int i = 0; i < 2; i++) {
            const int r = r8 + i * 32;
            const uint32_t off = SW128((uint32_t)(r * 128 + j8 * 16));
            const size_t g = (size_t)r * ldb + kc + j8 * 8;
            cp16(st + ST_BH + off, Bh + g);
            cp16(st + ST_BL + off, Bl + g);
        }
        asm volatile("cp.async.commit_group;" ::: "memory");
    };

    const int a_row = (lane & 15);
    const int a_k8  = ((lane >> 4) & 1) * 8;
    const int b_row = (lane & 7) + ((lane >> 4) & 1) * 8;
    const int b_k8  = ((lane >> 3) & 1) * 8;

    issue(0);

    for (int c = 0; c < kIters; c++) {
        if (c + 1 < kIters) {
            issue(c + 1);
            asm volatile("cp.async.wait_group 1;" ::: "memory");
        } else {
            asm volatile("cp.async.wait_group 0;" ::: "memory");
        }
        __syncthreads();

        const uint32_t st = sbase + (c & 1) * STAGE;
        #pragma unroll
        for (int ks = 0; ks < 4; ks++) {
            const int kbase = ks * 16;
            uint32_t ah[2][4], al[2][4];
            #pragma unroll
            for (int mi = 0; mi < 2; mi++) {
                const uint32_t off =
                    SW128((uint32_t)((wm + mi * 16 + a_row) * 128 + (kbase + a_k8) * 2));
                ldsm_x4(ah[mi], st + ST_AH + off);
                ldsm_x4(al[mi], st + ST_AL + off);
            }
            uint32_t bh[4][2], bl[4][2];
            #pragma unroll
            for (int p = 0; p < 2; p++) {
                const uint32_t off =
                    SW128((uint32_t)((wn + p * 16 + b_row) * 128 + (kbase + b_k8) * 2));
                uint32_t t[4];
                ldsm_x4(t, st + ST_BH + off);
                bh[2 * p][0] = t[0]; bh[2 * p][1] = t[1];
                bh[2 * p + 1][0] = t[2]; bh[2 * p + 1][1] = t[3];
                ldsm_x4(t, st + ST_BL + off);
                bl[2 * p][0] = t[0]; bl[2 * p][1] = t[1];
                bl[2 * p + 1][0] = t[2]; bl[2 * p + 1][1] = t[3];
            }
            #pragma unroll
            for (int mi = 0; mi < 2; mi++)
                #pragma unroll
                for (int ni = 0; ni < 4; ni++) {
                    mma_bf16(acc[mi][ni], ah[mi], bh[ni]);
                    mma_bf16(acc[mi][ni], ah[mi], bl[ni]);
                    mma_bf16(acc[mi][ni], al[mi], bh[ni]);
                }
        }
        __syncthreads();
    }
}

// --------------------------- conversion kernels -----------------------------
__global__ __launch_bounds__(256) void convert_x(const float* __restrict__ x) {
    size_t i = ((size_t)blockIdx.x * 256 + threadIdx.x) * 4;
    float4 v = *(const float4*)(x + i);
    __nv_bfloat16 h[4], l[4];
    float vv[4] = {v.x, v.y, v.z, v.w};
    #pragma unroll
    for (int j = 0; j < 4; j++) {
        h[j] = __float2bfloat16(vv[j]);
        l[j] = __float2bfloat16(vv[j] - __bfloat162float(h[j]));
    }
    *(__nv_bfloat162*)(Xhi + i)     = __nv_bfloat162(h[0], h[1]);
    *(__nv_bfloat162*)(Xhi + i + 2) = __nv_bfloat162(h[2], h[3]);
    *(__nv_bfloat162*)(Xlo + i)     = __nv_bfloat162(l[0], l[1]);
    *(__nv_bfloat162*)(Xlo + i + 2) = __nv_bfloat162(l[2], l[3]);
}

__global__ void convert_w(const float* __restrict__ Wq,
                          const float* __restrict__ Wk,
                          const float* __restrict__ Wv) {
    __shared__ float t[32][33];
    const int z = blockIdx.z;
    const float* W = (z == 0) ? Wq : ((z == 1) ? Wk : Wv);
    const int n0 = blockIdx.x * 32, k0 = blockIdx.y * 32;
    const int tx = threadIdx.x, ty = threadIdx.y;
    #pragma unroll
    for (int r = ty; r < 32; r += 8)
        t[r][tx] = W[(size_t)(k0 + r) * DIM + n0 + tx];
    __syncthreads();
    __nv_bfloat16* oh = Wthi + (size_t)z * DIM * DIM;
    __nv_bfloat16* ol = Wtlo + (size_t)z * DIM * DIM;
    #pragma unroll
    for (int r = ty; r < 32; r += 8) {
        float v = t[tx][r];
        __nv_bfloat16 h = __float2bfloat16(v);
        oh[(size_t)(n0 + r) * DIM + k0 + tx] = h;
        ol[(size_t)(n0 + r) * DIM + k0 + tx] = __float2bfloat16(v - __bfloat162float(h));
    }
}

// ---------------- QKV GEMM: Q/K as [s][d] hi/lo; V directly as Vt [d][s] ----
__global__ __launch_bounds__(256) void qkv_gemm_mma() {
    extern __shared__ char smg[];
    const int tid = threadIdx.x;
    const int wid = tid >> 5, lane = tid & 31;
    const int n0 = blockIdx.x * 64, m0 = blockIdx.y * 128, z = blockIdx.z;
    const int wm = (wid & 3) * 32, wn = (wid >> 2) * 32;

    float acc[2][4][4] = {};
    gemm_tile_db(Xhi + (size_t)m0 * DIM, Xlo + (size_t)m0 * DIM, DIM,
                 Wthi + (size_t)z * DIM * DIM + (size_t)n0 * DIM,
                 Wtlo + (size_t)z * DIM * DIM + (size_t)n0 * DIM, DIM,
                 DIM / 64, smg, acc);

    if (z == 2) {
        // --- V epilogue: transpose 32x32 warp tile via smem, write Vt[b][d][s]
        __syncthreads();   // smem stages free after mainloop
        __nv_bfloat16* th = (__nv_bfloat16*)smg + (size_t)wid * 2 * 32 * 34;
        __nv_bfloat16* tl = th + 32 * 34;
        #pragma unroll
        for (int mi = 0; mi < 2; mi++) {
            const int rl = mi * 16 + (lane >> 2);
            #pragma unroll
            for (int ni = 0; ni < 4; ni++) {
                const int cl = ni * 8 + (lane & 3) * 2;
                #pragma unroll
                for (int half = 0; half < 2; half++) {
                    const int r = rl + half * 8;
                    const float v0 = acc[mi][ni][half * 2 + 0];
                    const float v1 = acc[mi][ni][half * 2 + 1];
                    const __nv_bfloat16 h0 = __float2bfloat16(v0);
                    const __nv_bfloat16 h1 = __float2bfloat16(v1);
                    th[(cl + 0) * 34 + r] = h0;
                    th[(cl + 1) * 34 + r] = h1;
                    tl[(cl + 0) * 34 + r] = __float2bfloat16(v0 - __bfloat162float(h0));
                    tl[(cl + 1) * 34 + r] = __float2bfloat16(v1 - __bfloat162float(h1));
                }
            }
        }
        __syncwarp();
        const int b    = m0 >> 11;               // m0 / SEQ
        const int sloc = (m0 & (SEQ - 1)) + wm;  // s within batch
        __nv_bfloat16* vth = Vthi + (size_t)b * DIM * SEQ;
        __nv_bfloat16* vtl = Vtlo + (size_t)b * DIM * SEQ;
        #pragma unroll 4
        for (int c = 0; c < 32; c++) {
            const size_t o = (size_t)(n0 + wn + c) * SEQ + sloc + lane;
            vth[o] = th[c * 34 + lane];
            vtl[o] = tl[c * 34 + lane];
        }
        return;
    }

    __nv_bfloat16* Dh = (z == 0) ? Qhi : Khi;
    __nv_bfloat16* Dl = (z == 0) ? Qlo : Klo;

    #pragma unroll
    for (int mi = 0; mi < 2; mi++) {
        const int row0 = m0 + wm + mi * 16 + (lane >> 2);
        #pragma unroll
        for (int ni = 0; ni < 4; ni++) {
            const int col = n0 + wn + ni * 8 + (lane & 3) * 2;
            #pragma unroll
            for (int half = 0; half < 2; half++) {
                const float v0 = acc[mi][ni][half * 2 + 0];
                const float v1 = acc[mi][ni][half * 2 + 1];
                const __nv_bfloat16 h0 = __float2bfloat16(v0);
                const __nv_bfloat16 h1 = __float2bfloat16(v1);
                const size_t idx = (size_t)(row0 + half * 8) * DIM + col;
                *(__nv_bfloat162*)(Dh + idx) = __nv_bfloat162(h0, h1);
                *(__nv_bfloat162*)(Dl + idx) = __nv_bfloat162(
                    __float2bfloat16(v0 - __bfloat162float(h0)),
                    __float2bfloat16(v1 - __bfloat162float(h1)));
            }
        }
    }
}

// ---------------- S GEMM: Sg = Q @ K^T (triangular tiles, unscaled) ---------
__global__ __launch_bounds__(256) void s_gemm() {
    const int bn = blockIdx.x;
    const int bm = gridDim.y - 1 - blockIdx.y;   // heavy tiles first
    const int b  = blockIdx.z;
    if (bn > 2 * bm + 1) return;                 // tile fully above diagonal
    extern __shared__ char smg[];
    const int tid = threadIdx.x;
    const int wid = tid >> 5, lane = tid & 31;
    const int m0 = bm * 128, n0 = bn * 64;
    const int wm = (wid & 3) * 32, wn = (wid >> 2) * 32;

    const size_t boff = (size_t)b * SEQ * DIM;
    float acc[2][4][4] = {};
    gemm_tile_db(Qhi + boff + (size_t)m0 * DIM, Qlo + boff + (size_t)m0 * DIM, DIM,
                 Khi + boff + (size_t)n0 * DIM, Klo + boff + (size_t)n0 * DIM, DIM,
                 DIM / 64, smg, acc);

    float* S = Sg + (size_t)b * SEQ * SEQ;
    #pragma unroll
    for (int mi = 0; mi < 2; mi++) {
        const int row0 = m0 + wm + mi * 16 + (lane >> 2);
        #pragma unroll
        for (int ni = 0; ni < 4; ni++) {
            const int col = n0 + wn + ni * 8 + (lane & 3) * 2;
            *(float2*)(S + (size_t)row0 * SEQ + col) =
                make_float2(acc[mi][ni][0], acc[mi][ni][1]);
            *(float2*)(S + (size_t)(row0 + 8) * SEQ + col) =
                make_float2(acc[mi][ni][2], acc[mi][ni][3]);
        }
    }
}

// ---------------- softmax + hi/lo split: Sg -> Phi/Plo -----------------------
__global__ __launch_bounds__(256) void softmax_split() {
    __shared__ float ebuf[SEQ];
    __shared__ float red[8];
    const int q = blockIdx.x, b = blockIdx.y;
    const int n = q + 1;
    const int rowpad = ((q >> 7) << 7) + 128;
    const int tid = threadIdx.x, wid = tid >> 5, lane = tid & 31;
    const float scale = 0.03125f;

    const float* srow = Sg + ((size_t)b * SEQ + q) * SEQ;

    float mx = -1e30f;
    for (int i = tid; i < n; i += 256) mx = fmaxf(mx, srow[i] * scale);
    #pragma unroll
    for (int o = 16; o; o >>= 1) mx = fmaxf(mx, __shfl_xor_sync(0xffffffffu, mx, o));
    if (lane == 0) red[wid] = mx;
    __syncthreads();
    float m2 = red[0];
    #pragma unroll
    for (int i = 1; i < 8; i++) m2 = fmaxf(m2, red[i]);
    __syncthreads();

    float sum = 0.0f;
    for (int i = tid; i < n; i += 256) {
        float e = __expf(srow[i] * scale - m2);
        ebuf[i] = e;
        sum += e;
    }
    #pragma unroll
    for (int o = 16; o; o >>= 1) sum += __shfl_xor_sync(0xffffffffu, sum, o);
    if (lane == 0) red[wid] = sum;
    __syncthreads();
    float s2 = red[0];
    #pragma unroll
    for (int i = 1; i < 8; i++) s2 += red[i];
    const float inv = 1.0f / s2;

    __nv_bfloat16* ph = Phi + ((size_t)b * SEQ + q) * SEQ;
    __nv_bfloat16* pl = Plo + ((size_t)b * SEQ + q) * SEQ;
    for (int i = tid; i < rowpad; i += 256) {
        const float p = (i < n) ? ebuf[i] * inv : 0.0f;
        const __nv_bfloat16 h = __float2bfloat16(p);
        ph[i] = h;
        pl[i] = __float2bfloat16(p - __bfloat162float(h));
    }
}

// ---------------- O GEMM: out = P @ V (causal k-range) ----------------------
__global__ __launch_bounds__(256) void o_gemm(float* __restrict__ out) {
    extern __shared__ char smg[];
    const int tid = threadIdx.x;
    const int wid = tid >> 5, lane = tid & 31;
    const int bn = blockIdx.x;
    const int bm = gridDim.y - 1 - blockIdx.y;   // heavy rows first
    const int b  = blockIdx.z;
    const int m0 = bm * 128, n0 = bn * 64;
    const int wm = (wid & 3) * 32, wn = (wid >> 2) * 32;

    const size_t poff = (size_t)b * SEQ * SEQ;
    const size_t voff = (size_t)b * DIM * SEQ;
    float acc[2][4][4] = {};
    gemm_tile_db(Phi + poff + (size_t)m0 * SEQ, Plo + poff + (size_t)m0 * SEQ, SEQ,
                 Vthi + voff + (size_t)n0 * SEQ, Vtlo + voff + (size_t)n0 * SEQ, SEQ,
                 (m0 + 128) / 64, smg, acc);

    float* O = out + (size_t)b * SEQ * DIM;
    #pragma unroll
    for (int mi = 0; mi < 2; mi++) {
        const int row0 = m0 + wm + mi * 16 + (lane >> 2);
        #pragma unroll
        for (int ni = 0; ni < 4; ni++) {
            const int col = n0 + wn + ni * 8 + (lane & 3) * 2;
            *(float2*)(O + (size_t)row0 * DIM + col) =
                make_float2(acc[mi][ni][0], acc[mi][ni][1]);
            *(float2*)(O + (size_t)(row0 + 8) * DIM + col) =
                make_float2(acc[mi][ni][2], acc[mi][ni][3]);
        }
    }
}

// ---------------------------------------------------------------------------
extern "C" void kernel_launch(void* const* d_in, const int* in_sizes, int n_in,
                              void* d_out, int out_size)
{
    const float* x  = (const float*)d_in[0];
    const float* Wq = (const float*)d_in[1];
    const float* Wk = (const float*)d_in[2];
    const float* Wv = (const float*)d_in[3];
    float* out = (float*)d_out;

    cudaFuncSetAttribute(qkv_gemm_mma, cudaFuncAttributeMaxDynamicSharedMemorySize, GEMM_SMEM);
    cudaFuncSetAttribute(s_gemm,       cudaFuncAttributeMaxDynamicSharedMemorySize, GEMM_SMEM);
    cudaFuncSetAttribute(o_gemm,       cudaFuncAttributeMaxDynamicSharedMemorySize, GEMM_SMEM);

    // fp32 -> bf16 hi/lo
    convert_x<<<MTOT * DIM / (256 * 4), 256>>>(x);
    convert_w<<<dim3(DIM / 32, DIM / 32, 3), dim3(32, 8)>>>(Wq, Wk, Wv);

    // QKV projections (HMMA bf16x3, 2-stage cp.async; V written transposed)
    qkv_gemm_mma<<<dim3(DIM / 64, MTOT / 128, 3), 256, GEMM_SMEM>>>();

    // Scores (triangular), softmax, PV
    s_gemm<<<dim3(SEQ / 64, SEQ / 128, BATCH), 256, GEMM_SMEM>>>();
    softmax_split<<<dim3(SEQ, BATCH), 256>>>();
    o_gemm<<<dim3(DIM / 64, SEQ / 128, BATCH), 256, GEMM_SMEM>>>(out);
}

// round 9
// speedup vs baseline: 1.3300x; 1.0386x over previous
#include <cuda_runtime.h>
#include <cuda_bf16.h>
#include <cstdint>

#define BATCH 4
#define SEQ   2048
#define DIM   1024
#define MTOT  (BATCH*SEQ)

// ------------------------- device scratch (no allocs) -----------------------
__device__ __nv_bfloat16 Xhi[MTOT*(size_t)DIM];
__device__ __nv_bfloat16 Xlo[MTOT*(size_t)DIM];
__device__ __nv_bfloat16 Wthi[3*(size_t)DIM*DIM];   // [z][n][k]
__device__ __nv_bfloat16 Wtlo[3*(size_t)DIM*DIM];
__device__ __nv_bfloat16 Qhi[MTOT*(size_t)DIM];
__device__ __nv_bfloat16 Qlo[MTOT*(size_t)DIM];
__device__ __nv_bfloat16 Khi[MTOT*(size_t)DIM];
__device__ __nv_bfloat16 Klo[MTOT*(size_t)DIM];
__device__ __nv_bfloat16 Vthi[MTOT*(size_t)DIM];    // [b][d][s]
__device__ __nv_bfloat16 Vtlo[MTOT*(size_t)DIM];
__device__ float         Sg  [(size_t)BATCH*SEQ*SEQ];   // [b][q][k] (pre-scaled)
__device__ __nv_bfloat16 Phi [(size_t)BATCH*SEQ*SEQ];
__device__ __nv_bfloat16 Plo [(size_t)BATCH*SEQ*SEQ];

// ------------------------------ helpers -------------------------------------
__device__ __forceinline__ uint32_t smem_to_u32(const void* p) {
    uint32_t a;
    asm("{ .reg .u64 t; cvta.to.shared.u64 t, %1; cvt.u32.u64 %0, t; }"
        : "=r"(a) : "l"(p));
    return a;
}
#define SW128(off) ((off) ^ (((off) >> 3) & 0x70))

__device__ __forceinline__ void ldsm_x4(uint32_t* r, uint32_t addr) {
    asm volatile("ldmatrix.sync.aligned.m8n8.x4.shared.b16 {%0,%1,%2,%3}, [%4];"
                 : "=r"(r[0]), "=r"(r[1]), "=r"(r[2]), "=r"(r[3]) : "r"(addr));
}
__device__ __forceinline__ void mma_bf16(float* c, const uint32_t* a, const uint32_t* b) {
    asm volatile(
        "mma.sync.aligned.m16n8k16.row.col.f32.bf16.bf16.f32 "
        "{%0,%1,%2,%3}, {%4,%5,%6,%7}, {%8,%9}, {%0,%1,%2,%3};"
        : "+f"(c[0]), "+f"(c[1]), "+f"(c[2]), "+f"(c[3])
        : "r"(a[0]), "r"(a[1]), "r"(a[2]), "r"(a[3]), "r"(b[0]), "r"(b[1]));
}
__device__ __forceinline__ void cp16(uint32_t smem_dst, const void* gptr) {
    asm volatile("cp.async.cg.shared.global [%0], [%1], 16;"
                 :: "r"(smem_dst), "l"(gptr));
}

// ----------------- double-buffered bf16x3 mainloop (R5, proven) --------------
#define ST_AH 0
#define ST_AL 16384
#define ST_BH 32768
#define ST_BL 40960
#define STAGE 49152
#define GEMM_SMEM (2*STAGE)   // 98304

__device__ __forceinline__ void gemm_tile_db(
    const __nv_bfloat16* __restrict__ Ah, const __nv_bfloat16* __restrict__ Al, size_t lda,
    const __nv_bfloat16* __restrict__ Bh, const __nv_bfloat16* __restrict__ Bl, size_t ldb,
    int kIters, char* smem, float acc[2][4][4])
{
    const int tid = threadIdx.x;
    const int wid = tid >> 5, lane = tid & 31;
    const int wm = (wid & 3) * 32;
    const int wn = (wid >> 2) * 32;
    const uint32_t sbase = smem_to_u32(smem);

    const int r8 = tid >> 3, j8 = tid & 7;

    auto issue = [&](int c) {
        const int kc = c * 64;
        const uint32_t st = sbase + (c & 1) * STAGE;
        #pragma unroll
        for (int i = 0; i < 4; i++) {
            const int r = r8 + i * 32;
            const uint32_t off = SW128((uint32_t)(r * 128 + j8 * 16));
            const size_t g = (size_t)r * lda + kc + j8 * 8;
            cp16(st + ST_AH + off, Ah + g);
            cp16(st + ST_AL + off, Al + g);
        }
        #pragma unroll
        for (int i = 0; i < 2; i++) {
            const int r = r8 + i * 32;
            const uint32_t off = SW128((uint32_t)(r * 128 + j8 * 16));
            const size_t g = (size_t)r * ldb + kc + j8 * 8;
            cp16(st + ST_BH + off, Bh + g);
            cp16(st + ST_BL + off, Bl + g);
        }
        asm volatile("cp.async.commit_group;" ::: "memory");
    };

    const int a_row = (lane & 15);
    const int a_k8  = ((lane >> 4) & 1) * 8;
    const int b_row = (lane & 7) + ((lane >> 4) & 1) * 8;
    const int b_k8  = ((lane >> 3) & 1) * 8;

    issue(0);

    for (int c = 0; c < kIters; c++) {
        if (c + 1 < kIters) {
            issue(c + 1);
            asm volatile("cp.async.wait_group 1;" ::: "memory");
        } else {
            asm volatile("cp.async.wait_group 0;" ::: "memory");
        }
        __syncthreads();

        const uint32_t st = sbase + (c & 1) * STAGE;
        #pragma unroll
        for (int ks = 0; ks < 4; ks++) {
            const int kbase = ks * 16;
            uint32_t ah[2][4], al[2][4];
            #pragma unroll
            for (int mi = 0; mi < 2; mi++) {
                const uint32_t off =
                    SW128((uint32_t)((wm + mi * 16 + a_row) * 128 + (kbase + a_k8) * 2));
                ldsm_x4(ah[mi], st + ST_AH + off);
                ldsm_x4(al[mi], st + ST_AL + off);
            }
            uint32_t bh[4][2], bl[4][2];
            #pragma unroll
            for (int p = 0; p < 2; p++) {
                const uint32_t off =
                    SW128((uint32_t)((wn + p * 16 + b_row) * 128 + (kbase + b_k8) * 2));
                uint32_t t[4];
                ldsm_x4(t, st + ST_BH + off);
                bh[2 * p][0] = t[0]; bh[2 * p][1] = t[1];
                bh[2 * p + 1][0] = t[2]; bh[2 * p + 1][1] = t[3];
                ldsm_x4(t, st + ST_BL + off);
                bl[2 * p][0] = t[0]; bl[2 * p][1] = t[1];
                bl[2 * p + 1][0] = t[2]; bl[2 * p + 1][1] = t[3];
            }
            #pragma unroll
            for (int mi = 0; mi < 2; mi++)
                #pragma unroll
                for (int ni = 0; ni < 4; ni++) {
                    mma_bf16(acc[mi][ni], ah[mi], bh[ni]);
                    mma_bf16(acc[mi][ni], ah[mi], bl[ni]);
                    mma_bf16(acc[mi][ni], al[mi], bh[ni]);
                }
        }
        __syncthreads();
    }
}

// --------------------------- conversion kernels -----------------------------
__global__ __launch_bounds__(256) void convert_x(const float* __restrict__ x) {
    size_t i = ((size_t)blockIdx.x * 256 + threadIdx.x) * 4;
    float4 v = *(const float4*)(x + i);
    __nv_bfloat16 h[4], l[4];
    float vv[4] = {v.x, v.y, v.z, v.w};
    #pragma unroll
    for (int j = 0; j < 4; j++) {
        h[j] = __float2bfloat16(vv[j]);
        l[j] = __float2bfloat16(vv[j] - __bfloat162float(h[j]));
    }
    *(__nv_bfloat162*)(Xhi + i)     = __nv_bfloat162(h[0], h[1]);
    *(__nv_bfloat162*)(Xhi + i + 2) = __nv_bfloat162(h[2], h[3]);
    *(__nv_bfloat162*)(Xlo + i)     = __nv_bfloat162(l[0], l[1]);
    *(__nv_bfloat162*)(Xlo + i + 2) = __nv_bfloat162(l[2], l[3]);
}

__global__ void convert_w(const float* __restrict__ Wq,
                          const float* __restrict__ Wk,
                          const float* __restrict__ Wv) {
    __shared__ float t[32][33];
    const int z = blockIdx.z;
    const float* W = (z == 0) ? Wq : ((z == 1) ? Wk : Wv);
    const int n0 = blockIdx.x * 32, k0 = blockIdx.y * 32;
    const int tx = threadIdx.x, ty = threadIdx.y;
    #pragma unroll
    for (int r = ty; r < 32; r += 8)
        t[r][tx] = W[(size_t)(k0 + r) * DIM + n0 + tx];
    __syncthreads();
    __nv_bfloat16* oh = Wthi + (size_t)z * DIM * DIM;
    __nv_bfloat16* ol = Wtlo + (size_t)z * DIM * DIM;
    #pragma unroll
    for (int r = ty; r < 32; r += 8) {
        float v = t[tx][r];
        __nv_bfloat16 h = __float2bfloat16(v);
        oh[(size_t)(n0 + r) * DIM + k0 + tx] = h;
        ol[(size_t)(n0 + r) * DIM + k0 + tx] = __float2bfloat16(v - __bfloat162float(h));
    }
}

// ---------------- QK GEMM: Q/K as [s][d] hi/lo -------------------------------
__global__ __launch_bounds__(256) void qkv_gemm_mma() {
    extern __shared__ char smg[];
    const int tid = threadIdx.x;
    const int wid = tid >> 5, lane = tid & 31;
    const int n0 = blockIdx.x * 64, m0 = blockIdx.y * 128, z = blockIdx.z;
    const int wm = (wid & 3) * 32, wn = (wid >> 2) * 32;

    float acc[2][4][4] = {};
    gemm_tile_db(Xhi + (size_t)m0 * DIM, Xlo + (size_t)m0 * DIM, DIM,
                 Wthi + (size_t)z * DIM * DIM + (size_t)n0 * DIM,
                 Wtlo + (size_t)z * DIM * DIM + (size_t)n0 * DIM, DIM,
                 DIM / 64, smg, acc);

    __nv_bfloat16* Dh = (z == 0) ? Qhi : Khi;
    __nv_bfloat16* Dl = (z == 0) ? Qlo : Klo;

    #pragma unroll
    for (int mi = 0; mi < 2; mi++) {
        const int row0 = m0 + wm + mi * 16 + (lane >> 2);
        #pragma unroll
        for (int ni = 0; ni < 4; ni++) {
            const int col = n0 + wn + ni * 8 + (lane & 3) * 2;
            #pragma unroll
            for (int half = 0; half < 2; half++) {
                const float v0 = acc[mi][ni][half * 2 + 0];
                const float v1 = acc[mi][ni][half * 2 + 1];
                const __nv_bfloat16 h0 = __float2bfloat16(v0);
                const __nv_bfloat16 h1 = __float2bfloat16(v1);
                const size_t idx = (size_t)(row0 + half * 8) * DIM + col;
                *(__nv_bfloat162*)(Dh + idx) = __nv_bfloat162(h0, h1);
                *(__nv_bfloat162*)(Dl + idx) = __nv_bfloat162(
                    __float2bfloat16(v0 - __bfloat162float(h0)),
                    __float2bfloat16(v1 - __bfloat162float(h1)));
            }
        }
    }
}

// ---------------- fused launch: S = Q@K^T (triangular) + V projection -------
// grid (48, 16, 4): x<32 -> S-tile role; x>=32 -> V-projection role.
__global__ __launch_bounds__(256) void sv_gemm() {
    extern __shared__ char smg[];
    const int tid = threadIdx.x;
    const int wid = tid >> 5, lane = tid & 31;
    const int wm = (wid & 3) * 32, wn = (wid >> 2) * 32;

    if (blockIdx.x >= 32) {
        // ---- V projection role: vid in [0, 1024) -> (m_blk 64, n_blk 16) ----
        const int vid = (blockIdx.x - 32) + 16 * (blockIdx.y + 16 * blockIdx.z);
        const int n0 = (vid & 15) * 64;
        const int m0 = (vid >> 4) * 128;

        float acc[2][4][4] = {};
        gemm_tile_db(Xhi + (size_t)m0 * DIM, Xlo + (size_t)m0 * DIM, DIM,
                     Wthi + 2 * (size_t)DIM * DIM + (size_t)n0 * DIM,
                     Wtlo + 2 * (size_t)DIM * DIM + (size_t)n0 * DIM, DIM,
                     DIM / 64, smg, acc);

        // transpose 32x32 warp tile via smem, write Vt[b][d][s] (R8-proven)
        __syncthreads();
        __nv_bfloat16* th = (__nv_bfloat16*)smg + (size_t)wid * 2 * 32 * 34;
        __nv_bfloat16* tl = th + 32 * 34;
        #pragma unroll
        for (int mi = 0; mi < 2; mi++) {
            const int rl = mi * 16 + (lane >> 2);
            #pragma unroll
            for (int ni = 0; ni < 4; ni++) {
                const int cl = ni * 8 + (lane & 3) * 2;
                #pragma unroll
                for (int half = 0; half < 2; half++) {
                    const int r = rl + half * 8;
                    const float v0 = acc[mi][ni][half * 2 + 0];
                    const float v1 = acc[mi][ni][half * 2 + 1];
                    const __nv_bfloat16 h0 = __float2bfloat16(v0);
                    const __nv_bfloat16 h1 = __float2bfloat16(v1);
                    th[(cl + 0) * 34 + r] = h0;
                    th[(cl + 1) * 34 + r] = h1;
                    tl[(cl + 0) * 34 + r] = __float2bfloat16(v0 - __bfloat162float(h0));
                    tl[(cl + 1) * 34 + r] = __float2bfloat16(v1 - __bfloat162float(h1));
                }
            }
        }
        __syncwarp();
        const int b    = m0 >> 11;
        const int sloc = (m0 & (SEQ - 1)) + wm;
        __nv_bfloat16* vth = Vthi + (size_t)b * DIM * SEQ;
        __nv_bfloat16* vtl = Vtlo + (size_t)b * DIM * SEQ;
        #pragma unroll 4
        for (int c = 0; c < 32; c++) {
            const size_t o = (size_t)(n0 + wn + c) * SEQ + sloc + lane;
            vth[o] = th[c * 34 + lane];
            vtl[o] = tl[c * 34 + lane];
        }
        return;
    }

    // ---- S role (triangular, heavy tiles first, scale fused) ----
    const int bn = blockIdx.x;
    const int bm = gridDim.y - 1 - blockIdx.y;
    const int b  = blockIdx.z;
    if (bn > 2 * bm + 1) return;
    const int m0 = bm * 128, n0 = bn * 64;

    const size_t boff = (size_t)b * SEQ * DIM;
    float acc[2][4][4] = {};
    gemm_tile_db(Qhi + boff + (size_t)m0 * DIM, Qlo + boff + (size_t)m0 * DIM, DIM,
                 Khi + boff + (size_t)n0 * DIM, Klo + boff + (size_t)n0 * DIM, DIM,
                 DIM / 64, smg, acc);

    float* S = Sg + (size_t)b * SEQ * SEQ;
    const float scale = 0.03125f;
    #pragma unroll
    for (int mi = 0; mi < 2; mi++) {
        const int row0 = m0 + wm + mi * 16 + (lane >> 2);
        #pragma unroll
        for (int ni = 0; ni < 4; ni++) {
            const int col = n0 + wn + ni * 8 + (lane & 3) * 2;
            *(float2*)(S + (size_t)row0 * SEQ + col) =
                make_float2(acc[mi][ni][0] * scale, acc[mi][ni][1] * scale);
            *(float2*)(S + (size_t)(row0 + 8) * SEQ + col) =
                make_float2(acc[mi][ni][2] * scale, acc[mi][ni][3] * scale);
        }
    }
}

// ---------------- softmax + hi/lo split: Sg -> Phi/Plo -----------------------
// No max pass: scores are pre-scaled and bounded (|s| <= ~34), exp() is safe.
__global__ __launch_bounds__(256) void softmax_split() {
    __shared__ float4 ebuf4[SEQ / 4];
    __shared__ float red[8];
    const int q = blockIdx.x, b = blockIdx.y;
    const int rowpad4 = (((q >> 7) << 7) + 128) >> 2;   // float4 count
    const int tid = threadIdx.x, wid = tid >> 5, lane = tid & 31;

    const float4* srow4 = (const float4*)(Sg + ((size_t)b * SEQ + q) * SEQ);

    float sum = 0.0f;
    for (int i = tid; i < rowpad4; i += 256) {
        const float4 s4 = srow4[i];
        const int base = i * 4;
        float4 e;
        e.x = (base + 0 <= q) ? __expf(s4.x) : 0.0f;
        e.y = (base + 1 <= q) ? __expf(s4.y) : 0.0f;
        e.z = (base + 2 <= q) ? __expf(s4.z) : 0.0f;
        e.w = (base + 3 <= q) ? __expf(s4.w) : 0.0f;
        ebuf4[i] = e;
        sum += (e.x + e.y) + (e.z + e.w);
    }
    #pragma unroll
    for (int o = 16; o; o >>= 1) sum += __shfl_xor_sync(0xffffffffu, sum, o);
    if (lane == 0) red[wid] = sum;
    __syncthreads();
    float s2 = red[0];
    #pragma unroll
    for (int i = 1; i < 8; i++) s2 += red[i];
    const float inv = 1.0f / s2;

    uint2* ph = (uint2*)(Phi + ((size_t)b * SEQ + q) * SEQ);
    uint2* pl = (uint2*)(Plo + ((size_t)b * SEQ + q) * SEQ);
    for (int i = tid; i < rowpad4; i += 256) {
        const float4 e = ebuf4[i];
        const float p0 = e.x * inv, p1 = e.y * inv, p2 = e.z * inv, p3 = e.w * inv;
        const __nv_bfloat16 h0 = __float2bfloat16(p0);
        const __nv_bfloat16 h1 = __float2bfloat16(p1);
        const __nv_bfloat16 h2 = __float2bfloat16(p2);
        const __nv_bfloat16 h3 = __float2bfloat16(p3);
        __nv_bfloat162 hh0(h0, h1), hh1(h2, h3);
        __nv_bfloat162 ll0(__float2bfloat16(p0 - __bfloat162float(h0)),
                           __float2bfloat16(p1 - __bfloat162float(h1)));
        __nv_bfloat162 ll1(__float2bfloat16(p2 - __bfloat162float(h2)),
                           __float2bfloat16(p3 - __bfloat162float(h3)));
        ph[i] = make_uint2(*(uint32_t*)&hh0, *(uint32_t*)&hh1);
        pl[i] = make_uint2(*(uint32_t*)&ll0, *(uint32_t*)&ll1);
    }
}

// ---------------- O GEMM: out = P @ V (causal k-range) ----------------------
__global__ __launch_bounds__(256) void o_gemm(float* __restrict__ out) {
    extern __shared__ char smg[];
    const int tid = threadIdx.x;
    const int wid = tid >> 5, lane = tid & 31;
    const int bn = blockIdx.x;
    const int bm = gridDim.y - 1 - blockIdx.y;   // heavy rows first
    const int b  = blockIdx.z;
    const int m0 = bm * 128, n0 = bn * 64;
    const int wm = (wid & 3) * 32, wn = (wid >> 2) * 32;

    const size_t poff = (size_t)b * SEQ * SEQ;
    const size_t voff = (size_t)b * DIM * SEQ;
    float acc[2][4][4] = {};
    gemm_tile_db(Phi + poff + (size_t)m0 * SEQ, Plo + poff + (size_t)m0 * SEQ, SEQ,
                 Vthi + voff + (size_t)n0 * SEQ, Vtlo + voff + (size_t)n0 * SEQ, SEQ,
                 (m0 + 128) / 64, smg, acc);

    float* O = out + (size_t)b * SEQ * DIM;
    #pragma unroll
    for (int mi = 0; mi < 2; mi++) {
        const int row0 = m0 + wm + mi * 16 + (lane >> 2);
        #pragma unroll
        for (int ni = 0; ni < 4; ni++) {
            const int col = n0 + wn + ni * 8 + (lane & 3) * 2;
            *(float2*)(O + (size_t)row0 * DIM + col) =
                make_float2(acc[mi][ni][0], acc[mi][ni][1]);
            *(float2*)(O + (size_t)(row0 + 8) * DIM + col) =
                make_float2(acc[mi][ni][2], acc[mi][ni][3]);
        }
    }
}

// ---------------------------------------------------------------------------
extern "C" void kernel_launch(void* const* d_in, const int* in_sizes, int n_in,
                              void* d_out, int out_size)
{
    const float* x  = (const float*)d_in[0];
    const float* Wq = (const float*)d_in[1];
    const float* Wk = (const float*)d_in[2];
    const float* Wv = (const float*)d_in[3];
    float* out = (float*)d_out;

    cudaFuncSetAttribute(qkv_gemm_mma, cudaFuncAttributeMaxDynamicSharedMemorySize, GEMM_SMEM);
    cudaFuncSetAttribute(sv_gemm,      cudaFuncAttributeMaxDynamicSharedMemorySize, GEMM_SMEM);
    cudaFuncSetAttribute(o_gemm,       cudaFuncAttributeMaxDynamicSharedMemorySize, GEMM_SMEM);

    // fp32 -> bf16 hi/lo
    convert_x<<<MTOT * DIM / (256 * 4), 256>>>(x);
    convert_w<<<dim3(DIM / 32, DIM / 32, 3), dim3(32, 8)>>>(Wq, Wk, Wv);

    // Q,K projections only
    qkv_gemm_mma<<<dim3(DIM / 64, MTOT / 128, 2), 256, GEMM_SMEM>>>();

    // Fused: S scores (triangular, scaled) + V projection (transposed write)
    sv_gemm<<<dim3(48, 16, BATCH), 256, GEMM_SMEM>>>();

    // Softmax (no max pass) + P hi/lo split
    softmax_split<<<dim3(SEQ, BATCH), 256>>>();

    // O = P @ V
    o_gemm<<<dim3(DIM / 64, SEQ / 128, BATCH), 256, GEMM_SMEM>>>(out);
}

// round 10
// speedup vs baseline: 1.8334x; 1.3785x over previous
#include <cuda_runtime.h>
#include <cuda_fp16.h>
#include <cstdint>

#define BATCH 4
#define SEQ   2048
#define DIM   1024
#define MTOT  (BATCH*SEQ)

// ------------------------- device scratch (no allocs) -----------------------
__device__ __half Xh[MTOT*(size_t)DIM];
__device__ __half Xl[MTOT*(size_t)DIM];
__device__ __half Wth[3*(size_t)DIM*DIM];    // [z][n][k], fp16(W) transposed
__device__ __half Qh[MTOT*(size_t)DIM];
__device__ __half Ql[MTOT*(size_t)DIM];
__device__ __half Kh[MTOT*(size_t)DIM];      // rounded-B operand: hi only
__device__ __half Vth[MTOT*(size_t)DIM];     // [b][d][s], hi only
__device__ float  Sg [(size_t)BATCH*SEQ*SEQ];    // [b][q][k] (pre-scaled)
__device__ __half Ph [(size_t)BATCH*SEQ*SEQ];
__device__ __half Pl [(size_t)BATCH*SEQ*SEQ];

// ------------------------------ helpers -------------------------------------
__device__ __forceinline__ uint32_t smem_to_u32(const void* p) {
    uint32_t a;
    asm("{ .reg .u64 t; cvta.to.shared.u64 t, %1; cvt.u32.u64 %0, t; }"
        : "=r"(a) : "l"(p));
    return a;
}
#define SW128(off) ((off) ^ (((off) >> 3) & 0x70))

__device__ __forceinline__ void ldsm_x4(uint32_t* r, uint32_t addr) {
    asm volatile("ldmatrix.sync.aligned.m8n8.x4.shared.b16 {%0,%1,%2,%3}, [%4];"
                 : "=r"(r[0]), "=r"(r[1]), "=r"(r[2]), "=r"(r[3]) : "r"(addr));
}
__device__ __forceinline__ void mma_f16(float* c, const uint32_t* a, const uint32_t* b) {
    asm volatile(
        "mma.sync.aligned.m16n8k16.row.col.f32.f16.f16.f32 "
        "{%0,%1,%2,%3}, {%4,%5,%6,%7}, {%8,%9}, {%0,%1,%2,%3};"
        : "+f"(c[0]), "+f"(c[1]), "+f"(c[2]), "+f"(c[3])
        : "r"(a[0]), "r"(a[1]), "r"(a[2]), "r"(a[3]), "r"(b[0]), "r"(b[1]));
}
__device__ __forceinline__ void cp16(uint32_t smem_dst, const void* gptr) {
    asm volatile("cp.async.cg.shared.global [%0], [%1], 16;"
                 :: "r"(smem_dst), "l"(gptr));
}
__device__ __forceinline__ uint32_t pack_half2(__half a, __half b) {
    __half2 h2 = __halves2half2(a, b);
    return *(uint32_t*)&h2;
}

// ----------------- double-buffered fp16x2 mainloop ---------------------------
// Block tile 128m x 64n x 64k, 8 warps (warp tile 32x32), cp.async 2-stage.
// C = (Ah + Al) . Bh  (full-A x rounded-B; error = A.Bres ~ 2^-12)
// Stage layout (40 KB): Ah[16K] Al[16K] Bh[8K].
#define ST_AH 0
#define ST_AL 16384
#define ST_BH 32768
#define STAGE 40960
#define GEMM_SMEM (2*STAGE)   // 81920

__device__ __forceinline__ void gemm_tile_db(
    const __half* __restrict__ Ahp, const __half* __restrict__ Alp, size_t lda,
    const __half* __restrict__ Bhp, size_t ldb,
    int kIters, char* smem, float acc[2][4][4])
{
    const int tid = threadIdx.x;
    const int wid = tid >> 5, lane = tid & 31;
    const int wm = (wid & 3) * 32;
    const int wn = (wid >> 2) * 32;
    const uint32_t sbase = smem_to_u32(smem);

    const int r8 = tid >> 3, j8 = tid & 7;

    auto issue = [&](int c) {
        const int kc = c * 64;
        const uint32_t st = sbase + (c & 1) * STAGE;
        #pragma unroll
        for (int i = 0; i < 4; i++) {
            const int r = r8 + i * 32;
            const uint32_t off = SW128((uint32_t)(r * 128 + j8 * 16));
            const size_t g = (size_t)r * lda + kc + j8 * 8;
            cp16(st + ST_AH + off, Ahp + g);
            cp16(st + ST_AL + off, Alp + g);
        }
        #pragma unroll
        for (int i = 0; i < 2; i++) {
            const int r = r8 + i * 32;
            const uint32_t off = SW128((uint32_t)(r * 128 + j8 * 16));
            const size_t g = (size_t)r * ldb + kc + j8 * 8;
            cp16(st + ST_BH + off, Bhp + g);
        }
        asm volatile("cp.async.commit_group;" ::: "memory");
    };

    const int a_row = (lane & 15);
    const int a_k8  = ((lane >> 4) & 1) * 8;
    const int b_row = (lane & 7) + ((lane >> 4) & 1) * 8;
    const int b_k8  = ((lane >> 3) & 1) * 8;

    issue(0);

    for (int c = 0; c < kIters; c++) {
        if (c + 1 < kIters) {
            issue(c + 1);
            asm volatile("cp.async.wait_group 1;" ::: "memory");
        } else {
            asm volatile("cp.async.wait_group 0;" ::: "memory");
        }
        __syncthreads();

        const uint32_t st = sbase + (c & 1) * STAGE;
        #pragma unroll
        for (int ks = 0; ks < 4; ks++) {
            const int kbase = ks * 16;
            uint32_t ah[2][4], al[2][4];
            #pragma unroll
            for (int mi = 0; mi < 2; mi++) {
                const uint32_t off =
                    SW128((uint32_t)((wm + mi * 16 + a_row) * 128 + (kbase + a_k8) * 2));
                ldsm_x4(ah[mi], st + ST_AH + off);
                ldsm_x4(al[mi], st + ST_AL + off);
            }
            uint32_t bh[4][2];
            #pragma unroll
            for (int p = 0; p < 2; p++) {
                const uint32_t off =
                    SW128((uint32_t)((wn + p * 16 + b_row) * 128 + (kbase + b_k8) * 2));
                uint32_t t[4];
                ldsm_x4(t, st + ST_BH + off);
                bh[2 * p][0] = t[0]; bh[2 * p][1] = t[1];
                bh[2 * p + 1][0] = t[2]; bh[2 * p + 1][1] = t[3];
            }
            #pragma unroll
            for (int mi = 0; mi < 2; mi++)
                #pragma unroll
                for (int ni = 0; ni < 4; ni++) {
                    mma_f16(acc[mi][ni], ah[mi], bh[ni]);
                    mma_f16(acc[mi][ni], al[mi], bh[ni]);
                }
        }
        __syncthreads();
    }
}

// --------------------------- conversion kernels -----------------------------
__global__ __launch_bounds__(256) void convert_x(const float* __restrict__ x) {
    size_t i = ((size_t)blockIdx.x * 256 + threadIdx.x) * 4;
    float4 v = *(const float4*)(x + i);
    float vv[4] = {v.x, v.y, v.z, v.w};
    __half h[4], l[4];
    #pragma unroll
    for (int j = 0; j < 4; j++) {
        h[j] = __float2half_rn(vv[j]);
        l[j] = __float2half_rn(vv[j] - __half2float(h[j]));
    }
    *(uint32_t*)(Xh + i)     = pack_half2(h[0], h[1]);
    *(uint32_t*)(Xh + i + 2) = pack_half2(h[2], h[3]);
    *(uint32_t*)(Xl + i)     = pack_half2(l[0], l[1]);
    *(uint32_t*)(Xl + i + 2) = pack_half2(l[2], l[3]);
}

// Transpose W, hi only: Wth[z][n][k] = fp16(W[z][k][n])
__global__ void convert_w(const float* __restrict__ Wq,
                          const float* __restrict__ Wk,
                          const float* __restrict__ Wv) {
    __shared__ float t[32][33];
    const int z = blockIdx.z;
    const float* W = (z == 0) ? Wq : ((z == 1) ? Wk : Wv);
    const int n0 = blockIdx.x * 32, k0 = blockIdx.y * 32;
    const int tx = threadIdx.x, ty = threadIdx.y;
    #pragma unroll
    for (int r = ty; r < 32; r += 8)
        t[r][tx] = W[(size_t)(k0 + r) * DIM + n0 + tx];
    __syncthreads();
    __half* oh = Wth + (size_t)z * DIM * DIM;
    #pragma unroll
    for (int r = ty; r < 32; r += 8)
        oh[(size_t)(n0 + r) * DIM + k0 + tx] = __float2half_rn(t[tx][r]);
}

// ---------------- QK GEMM: Q as hi/lo, K as hi only --------------------------
__global__ __launch_bounds__(256) void qk_gemm() {
    extern __shared__ char smg[];
    const int tid = threadIdx.x;
    const int wid = tid >> 5, lane = tid & 31;
    const int n0 = blockIdx.x * 64, m0 = blockIdx.y * 128, z = blockIdx.z;
    const int wm = (wid & 3) * 32, wn = (wid >> 2) * 32;

    float acc[2][4][4] = {};
    gemm_tile_db(Xh + (size_t)m0 * DIM, Xl + (size_t)m0 * DIM, DIM,
                 Wth + (size_t)z * DIM * DIM + (size_t)n0 * DIM, DIM,
                 DIM / 64, smg, acc);

    #pragma unroll
    for (int mi = 0; mi < 2; mi++) {
        const int row0 = m0 + wm + mi * 16 + (lane >> 2);
        #pragma unroll
        for (int ni = 0; ni < 4; ni++) {
            const int col = n0 + wn + ni * 8 + (lane & 3) * 2;
            #pragma unroll
            for (int half = 0; half < 2; half++) {
                const float v0 = acc[mi][ni][half * 2 + 0];
                const float v1 = acc[mi][ni][half * 2 + 1];
                const __half h0 = __float2half_rn(v0);
                const __half h1 = __float2half_rn(v1);
                const size_t idx = (size_t)(row0 + half * 8) * DIM + col;
                if (z == 0) {
                    *(uint32_t*)(Qh + idx) = pack_half2(h0, h1);
                    *(uint32_t*)(Ql + idx) = pack_half2(
                        __float2half_rn(v0 - __half2float(h0)),
                        __float2half_rn(v1 - __half2float(h1)));
                } else {
                    *(uint32_t*)(Kh + idx) = pack_half2(h0, h1);
                }
            }
        }
    }
}

// ---------------- fused launch: S = Q@K^T (triangular) + V projection -------
// grid (48, 16, 4): x<32 -> S-tile role; x>=32 -> V-projection role.
__global__ __launch_bounds__(256) void sv_gemm() {
    extern __shared__ char smg[];
    const int tid = threadIdx.x;
    const int wid = tid >> 5, lane = tid & 31;
    const int wm = (wid & 3) * 32, wn = (wid >> 2) * 32;

    if (blockIdx.x >= 32) {
        // ---- V projection role: vid in [0, 1024) ----
        const int vid = (blockIdx.x - 32) + 16 * (blockIdx.y + 16 * blockIdx.z);
        const int n0 = (vid & 15) * 64;
        const int m0 = (vid >> 4) * 128;

        float acc[2][4][4] = {};
        gemm_tile_db(Xh + (size_t)m0 * DIM, Xl + (size_t)m0 * DIM, DIM,
                     Wth + 2 * (size_t)DIM * DIM + (size_t)n0 * DIM, DIM,
                     DIM / 64, smg, acc);

        // transpose 32x32 warp tile via smem, write Vt[b][d][s] (hi only)
        __syncthreads();
        __half* th = (__half*)smg + (size_t)wid * 32 * 34;
        #pragma unroll
        for (int mi = 0; mi < 2; mi++) {
            const int rl = mi * 16 + (lane >> 2);
            #pragma unroll
            for (int ni = 0; ni < 4; ni++) {
                const int cl = ni * 8 + (lane & 3) * 2;
                #pragma unroll
                for (int half = 0; half < 2; half++) {
                    const int r = rl + half * 8;
                    th[(cl + 0) * 34 + r] = __float2half_rn(acc[mi][ni][half * 2 + 0]);
                    th[(cl + 1) * 34 + r] = __float2half_rn(acc[mi][ni][half * 2 + 1]);
                }
            }
        }
        __syncwarp();
        const int b    = m0 >> 11;
        const int sloc = (m0 & (SEQ - 1)) + wm;
        __half* vth = Vth + (size_t)b * DIM * SEQ;
        #pragma unroll 4
        for (int c = 0; c < 32; c++)
            vth[(size_t)(n0 + wn + c) * SEQ + sloc + lane] = th[c * 34 + lane];
        return;
    }

    // ---- S role (triangular, heavy tiles first, scale fused) ----
    const int bn = blockIdx.x;
    const int bm = gridDim.y - 1 - blockIdx.y;
    const int b  = blockIdx.z;
    if (bn > 2 * bm + 1) return;
    const int m0 = bm * 128, n0 = bn * 64;

    const size_t boff = (size_t)b * SEQ * DIM;
    float acc[2][4][4] = {};
    gemm_tile_db(Qh + boff + (size_t)m0 * DIM, Ql + boff + (size_t)m0 * DIM, DIM,
                 Kh + boff + (size_t)n0 * DIM, DIM,
                 DIM / 64, smg, acc);

    float* S = Sg + (size_t)b * SEQ * SEQ;
    const float scale = 0.03125f;
    #pragma unroll
    for (int mi = 0; mi < 2; mi++) {
        const int row0 = m0 + wm + mi * 16 + (lane >> 2);
        #pragma unroll
        for (int ni = 0; ni < 4; ni++) {
            const int col = n0 + wn + ni * 8 + (lane & 3) * 2;
            *(float2*)(S + (size_t)row0 * SEQ + col) =
                make_float2(acc[mi][ni][0] * scale, acc[mi][ni][1] * scale);
            *(float2*)(S + (size_t)(row0 + 8) * SEQ + col) =
                make_float2(acc[mi][ni][2] * scale, acc[mi][ni][3] * scale);
        }
    }
}

// ---------------- softmax + fp16 hi/lo split: Sg -> Ph/Pl --------------------
// No max pass: scores are pre-scaled and bounded (|s| <= ~34), exp() is safe.
__global__ __launch_bounds__(256) void softmax_split() {
    __shared__ float4 ebuf4[SEQ / 4];
    __shared__ float red[8];
    const int q = blockIdx.x, b = blockIdx.y;
    const int rowpad4 = (((q >> 7) << 7) + 128) >> 2;
    const int tid = threadIdx.x, wid = tid >> 5, lane = tid & 31;

    const float4* srow4 = (const float4*)(Sg + ((size_t)b * SEQ + q) * SEQ);

    float sum = 0.0f;
    for (int i = tid; i < rowpad4; i += 256) {
        const float4 s4 = srow4[i];
        const int base = i * 4;
        float4 e;
        e.x = (base + 0 <= q) ? __expf(s4.x) : 0.0f;
        e.y = (base + 1 <= q) ? __expf(s4.y) : 0.0f;
        e.z = (base + 2 <= q) ? __expf(s4.z) : 0.0f;
        e.w = (base + 3 <= q) ? __expf(s4.w) : 0.0f;
        ebuf4[i] = e;
        sum += (e.x + e.y) + (e.z + e.w);
    }
    #pragma unroll
    for (int o = 16; o; o >>= 1) sum += __shfl_xor_sync(0xffffffffu, sum, o);
    if (lane == 0) red[wid] = sum;
    __syncthreads();
    float s2 = red[0];
    #pragma unroll
    for (int i = 1; i < 8; i++) s2 += red[i];
    const float inv = 1.0f / s2;

    uint2* ph = (uint2*)(Ph + ((size_t)b * SEQ + q) * SEQ);
    uint2* pl = (uint2*)(Pl + ((size_t)b * SEQ + q) * SEQ);
    for (int i = tid; i < rowpad4; i += 256) {
        const float4 e = ebuf4[i];
        const float p0 = e.x * inv, p1 = e.y * inv, p2 = e.z * inv, p3 = e.w * inv;
        const __half h0 = __float2half_rn(p0);
        const __half h1 = __float2half_rn(p1);
        const __half h2 = __float2half_rn(p2);
        const __half h3 = __float2half_rn(p3);
        ph[i] = make_uint2(pack_half2(h0, h1), pack_half2(h2, h3));
        pl[i] = make_uint2(
            pack_half2(__float2half_rn(p0 - __half2float(h0)),
                       __float2half_rn(p1 - __half2float(h1))),
            pack_half2(__float2half_rn(p2 - __half2float(h2)),
                       __float2half_rn(p3 - __half2float(h3))));
    }
}

// ---------------- O GEMM: out = P @ V (causal k-range) ----------------------
__global__ __launch_bounds__(256) void o_gemm(float* __restrict__ out) {
    extern __shared__ char smg[];
    const int tid = threadIdx.x;
    const int wid = tid >> 5, lane = tid & 31;
    const int bn = blockIdx.x;
    const int bm = gridDim.y - 1 - blockIdx.y;   // heavy rows first
    const int b  = blockIdx.z;
    const int m0 = bm * 128, n0 = bn * 64;
    const int wm = (wid & 3) * 32, wn = (wid >> 2) * 32;

    const size_t poff = (size_t)b * SEQ * SEQ;
    const size_t voff = (size_t)b * DIM * SEQ;
    float acc[2][4][4] = {};
    gemm_tile_db(Ph + poff + (size_t)m0 * SEQ, Pl + poff + (size_t)m0 * SEQ, SEQ,
                 Vth + voff + (size_t)n0 * SEQ, SEQ,
                 (m0 + 128) / 64, smg, acc);

    float* O = out + (size_t)b * SEQ * DIM;
    #pragma unroll
    for (int mi = 0; mi < 2; mi++) {
        const int row0 = m0 + wm + mi * 16 + (lane >> 2);
        #pragma unroll
        for (int ni = 0; ni < 4; ni++) {
            const int col = n0 + wn + ni * 8 + (lane & 3) * 2;
            *(float2*)(O + (size_t)row0 * DIM + col) =
                make_float2(acc[mi][ni][0], acc[mi][ni][1]);
            *(float2*)(O + (size_t)(row0 + 8) * DIM + col) =
                make_float2(acc[mi][ni][2], acc[mi][ni][3]);
        }
    }
}

// ---------------------------------------------------------------------------
extern "C" void kernel_launch(void* const* d_in, const int* in_sizes, int n_in,
                              void* d_out, int out_size)
{
    const float* x  = (const float*)d_in[0];
    const float* Wq = (const float*)d_in[1];
    const float* Wk = (const float*)d_in[2];
    const float* Wv = (const float*)d_in[3];
    float* out = (float*)d_out;

    cudaFuncSetAttribute(qk_gemm, cudaFuncAttributeMaxDynamicSharedMemorySize, GEMM_SMEM);
    cudaFuncSetAttribute(sv_gemm, cudaFuncAttributeMaxDynamicSharedMemorySize, GEMM_SMEM);
    cudaFuncSetAttribute(o_gemm,  cudaFuncAttributeMaxDynamicSharedMemorySize, GEMM_SMEM);

    // fp32 -> fp16 (hi/lo for X, hi-only transposed for W)
    convert_x<<<MTOT * DIM / (256 * 4), 256>>>(x);
    convert_w<<<dim3(DIM / 32, DIM / 32, 3), dim3(32, 8)>>>(Wq, Wk, Wv);

    // Q,K projections (fp16 2-pass)
    qk_gemm<<<dim3(DIM / 64, MTOT / 128, 2), 256, GEMM_SMEM>>>();

    // Fused: S scores (triangular, scaled) + V projection (transposed write)
    sv_gemm<<<dim3(48, 16, BATCH), 256, GEMM_SMEM>>>();

    // Softmax (no max pass) + P fp16 hi/lo split
    softmax_split<<<dim3(SEQ, BATCH), 256>>>();

    // O = P @ V
    o_gemm<<<dim3(DIM / 64, SEQ / 128, BATCH), 256, GEMM_SMEM>>>(out);
}

// round 11
// speedup vs baseline: 2.1164x; 1.1544x over previous
#include <cuda_runtime.h>
#include <cuda_fp16.h>
#include <cstdint>

#define BATCH 4
#define SEQ   2048
#define DIM   1024
#define MTOT  (BATCH*SEQ)

// ------------------------- device scratch (no allocs) -----------------------
__device__ __half Xh[MTOT*(size_t)DIM];
__device__ __half Xl[MTOT*(size_t)DIM];
__device__ __half Wth[3*(size_t)DIM*DIM];    // [z][n][k], fp16(W) transposed
__device__ __half Qh[MTOT*(size_t)DIM];
__device__ __half Ql[MTOT*(size_t)DIM];
__device__ __half Kh[MTOT*(size_t)DIM];      // rounded-B operand: hi only
__device__ __half Vth[MTOT*(size_t)DIM];     // [b][d][s], hi only
__device__ float  Sg [(size_t)BATCH*SEQ*SEQ];    // [b][q][k] (pre-scaled)
__device__ __half Ph [(size_t)BATCH*SEQ*SEQ];
__device__ __half Pl [(size_t)BATCH*SEQ*SEQ];

// ------------------------------ helpers -------------------------------------
__device__ __forceinline__ uint32_t smem_to_u32(const void* p) {
    uint32_t a;
    asm("{ .reg .u64 t; cvta.to.shared.u64 t, %1; cvt.u32.u64 %0, t; }"
        : "=r"(a) : "l"(p));
    return a;
}
#define SW128(off) ((off) ^ (((off) >> 3) & 0x70))

__device__ __forceinline__ void ldsm_x4(uint32_t* r, uint32_t addr) {
    asm volatile("ldmatrix.sync.aligned.m8n8.x4.shared.b16 {%0,%1,%2,%3}, [%4];"
                 : "=r"(r[0]), "=r"(r[1]), "=r"(r[2]), "=r"(r[3]) : "r"(addr));
}
__device__ __forceinline__ void mma_f16(float* c, const uint32_t* a, const uint32_t* b) {
    asm volatile(
        "mma.sync.aligned.m16n8k16.row.col.f32.f16.f16.f32 "
        "{%0,%1,%2,%3}, {%4,%5,%6,%7}, {%8,%9}, {%0,%1,%2,%3};"
        : "+f"(c[0]), "+f"(c[1]), "+f"(c[2]), "+f"(c[3])
        : "r"(a[0]), "r"(a[1]), "r"(a[2]), "r"(a[3]), "r"(b[0]), "r"(b[1]));
}
__device__ __forceinline__ void cp16(uint32_t smem_dst, const void* gptr) {
    asm volatile("cp.async.cg.shared.global [%0], [%1], 16;"
                 :: "r"(smem_dst), "l"(gptr));
}
__device__ __forceinline__ uint32_t pack_half2(__half a, __half b) {
    __half2 h2 = __halves2half2(a, b);
    return *(uint32_t*)&h2;
}

// ----------------- double-buffered fp16x2 mainloop (R10, proven) -------------
// Block tile 128m x 64n x 64k, 8 warps (warp tile 32x32), cp.async 2-stage.
// C = (Ah + Al) . Bh ; stage (40 KB): Ah[16K] Al[16K] Bh[8K].
#define ST_AH 0
#define ST_AL 16384
#define ST_BH 32768
#define STAGE 40960
#define GEMM_SMEM (2*STAGE)   // 81920

__device__ __forceinline__ void gemm_tile_db(
    const __half* __restrict__ Ahp, const __half* __restrict__ Alp, size_t lda,
    const __half* __restrict__ Bhp, size_t ldb,
    int kIters, char* smem, float acc[2][4][4])
{
    const int tid = threadIdx.x;
    const int wid = tid >> 5, lane = tid & 31;
    const int wm = (wid & 3) * 32;
    const int wn = (wid >> 2) * 32;
    const uint32_t sbase = smem_to_u32(smem);

    const int r8 = tid >> 3, j8 = tid & 7;

    auto issue = [&](int c) {
        const int kc = c * 64;
        const uint32_t st = sbase + (c & 1) * STAGE;
        #pragma unroll
        for (int i = 0; i < 4; i++) {
            const int r = r8 + i * 32;
            const uint32_t off = SW128((uint32_t)(r * 128 + j8 * 16));
            const size_t g = (size_t)r * lda + kc + j8 * 8;
            cp16(st + ST_AH + off, Ahp + g);
            cp16(st + ST_AL + off, Alp + g);
        }
        #pragma unroll
        for (int i = 0; i < 2; i++) {
            const int r = r8 + i * 32;
            const uint32_t off = SW128((uint32_t)(r * 128 + j8 * 16));
            const size_t g = (size_t)r * ldb + kc + j8 * 8;
            cp16(st + ST_BH + off, Bhp + g);
        }
        asm volatile("cp.async.commit_group;" ::: "memory");
    };

    const int a_row = (lane & 15);
    const int a_k8  = ((lane >> 4) & 1) * 8;
    const int b_row = (lane & 7) + ((lane >> 4) & 1) * 8;
    const int b_k8  = ((lane >> 3) & 1) * 8;

    issue(0);

    for (int c = 0; c < kIters; c++) {
        if (c + 1 < kIters) {
            issue(c + 1);
            asm volatile("cp.async.wait_group 1;" ::: "memory");
        } else {
            asm volatile("cp.async.wait_group 0;" ::: "memory");
        }
        __syncthreads();

        const uint32_t st = sbase + (c & 1) * STAGE;
        #pragma unroll
        for (int ks = 0; ks < 4; ks++) {
            const int kbase = ks * 16;
            uint32_t ah[2][4], al[2][4];
            #pragma unroll
            for (int mi = 0; mi < 2; mi++) {
                const uint32_t off =
                    SW128((uint32_t)((wm + mi * 16 + a_row) * 128 + (kbase + a_k8) * 2));
                ldsm_x4(ah[mi], st + ST_AH + off);
                ldsm_x4(al[mi], st + ST_AL + off);
            }
            uint32_t bh[4][2];
            #pragma unroll
            for (int p = 0; p < 2; p++) {
                const uint32_t off =
                    SW128((uint32_t)((wn + p * 16 + b_row) * 128 + (kbase + b_k8) * 2));
                uint32_t t[4];
                ldsm_x4(t, st + ST_BH + off);
                bh[2 * p][0] = t[0]; bh[2 * p][1] = t[1];
                bh[2 * p + 1][0] = t[2]; bh[2 * p + 1][1] = t[3];
            }
            #pragma unroll
            for (int mi = 0; mi < 2; mi++)
                #pragma unroll
                for (int ni = 0; ni < 4; ni++) {
                    mma_f16(acc[mi][ni], ah[mi], bh[ni]);
                    mma_f16(acc[mi][ni], al[mi], bh[ni]);
                }
        }
        __syncthreads();
    }
}

// ----------------- 1-pass variant: C = Ah . Bh (rounded-B outputs) ----------
// Stage (24 KB): Ah[16K] Bh[8K]. Same skeleton, half the MMAs.
#define ST1_BH 16384
#define STAGE1 24576

__device__ __forceinline__ void gemm_tile_1p(
    const __half* __restrict__ Ahp, size_t lda,
    const __half* __restrict__ Bhp, size_t ldb,
    int kIters, char* smem, float acc[2][4][4])
{
    const int tid = threadIdx.x;
    const int wid = tid >> 5, lane = tid & 31;
    const int wm = (wid & 3) * 32;
    const int wn = (wid >> 2) * 32;
    const uint32_t sbase = smem_to_u32(smem);

    const int r8 = tid >> 3, j8 = tid & 7;

    auto issue = [&](int c) {
        const int kc = c * 64;
        const uint32_t st = sbase + (c & 1) * STAGE1;
        #pragma unroll
        for (int i = 0; i < 4; i++) {
            const int r = r8 + i * 32;
            const uint32_t off = SW128((uint32_t)(r * 128 + j8 * 16));
            cp16(st + off, Ahp + (size_t)r * lda + kc + j8 * 8);
        }
        #pragma unroll
        for (int i = 0; i < 2; i++) {
            const int r = r8 + i * 32;
            const uint32_t off = SW128((uint32_t)(r * 128 + j8 * 16));
            cp16(st + ST1_BH + off, Bhp + (size_t)r * ldb + kc + j8 * 8);
        }
        asm volatile("cp.async.commit_group;" ::: "memory");
    };

    const int a_row = (lane & 15);
    const int a_k8  = ((lane >> 4) & 1) * 8;
    const int b_row = (lane & 7) + ((lane >> 4) & 1) * 8;
    const int b_k8  = ((lane >> 3) & 1) * 8;

    issue(0);

    for (int c = 0; c < kIters; c++) {
        if (c + 1 < kIters) {
            issue(c + 1);
            asm volatile("cp.async.wait_group 1;" ::: "memory");
        } else {
            asm volatile("cp.async.wait_group 0;" ::: "memory");
        }
        __syncthreads();

        const uint32_t st = sbase + (c & 1) * STAGE1;
        #pragma unroll
        for (int ks = 0; ks < 4; ks++) {
            const int kbase = ks * 16;
            uint32_t ah[2][4];
            #pragma unroll
            for (int mi = 0; mi < 2; mi++) {
                const uint32_t off =
                    SW128((uint32_t)((wm + mi * 16 + a_row) * 128 + (kbase + a_k8) * 2));
                ldsm_x4(ah[mi], st + off);
            }
            uint32_t bh[4][2];
            #pragma unroll
            for (int p = 0; p < 2; p++) {
                const uint32_t off =
                    SW128((uint32_t)((wn + p * 16 + b_row) * 128 + (kbase + b_k8) * 2));
                uint32_t t[4];
                ldsm_x4(t, st + ST1_BH + off);
                bh[2 * p][0] = t[0]; bh[2 * p][1] = t[1];
                bh[2 * p + 1][0] = t[2]; bh[2 * p + 1][1] = t[3];
            }
            #pragma unroll
            for (int mi = 0; mi < 2; mi++)
                #pragma unroll
                for (int ni = 0; ni < 4; ni++)
                    mma_f16(acc[mi][ni], ah[mi], bh[ni]);
        }
        __syncthreads();
    }
}

// --------------------------- conversion kernels -----------------------------
__global__ __launch_bounds__(256) void convert_x(const float* __restrict__ x) {
    size_t i = ((size_t)blockIdx.x * 256 + threadIdx.x) * 4;
    float4 v = *(const float4*)(x + i);
    float vv[4] = {v.x, v.y, v.z, v.w};
    __half h[4], l[4];
    #pragma unroll
    for (int j = 0; j < 4; j++) {
        h[j] = __float2half_rn(vv[j]);
        l[j] = __float2half_rn(vv[j] - __half2float(h[j]));
    }
    *(uint32_t*)(Xh + i)     = pack_half2(h[0], h[1]);
    *(uint32_t*)(Xh + i + 2) = pack_half2(h[2], h[3]);
    *(uint32_t*)(Xl + i)     = pack_half2(l[0], l[1]);
    *(uint32_t*)(Xl + i + 2) = pack_half2(l[2], l[3]);
}

// Transpose W, hi only: Wth[z][n][k] = fp16(W[z][k][n])
__global__ void convert_w(const float* __restrict__ Wq,
                          const float* __restrict__ Wk,
                          const float* __restrict__ Wv) {
    __shared__ float t[32][33];
    const int z = blockIdx.z;
    const float* W = (z == 0) ? Wq : ((z == 1) ? Wk : Wv);
    const int n0 = blockIdx.x * 32, k0 = blockIdx.y * 32;
    const int tx = threadIdx.x, ty = threadIdx.y;
    #pragma unroll
    for (int r = ty; r < 32; r += 8)
        t[r][tx] = W[(size_t)(k0 + r) * DIM + n0 + tx];
    __syncthreads();
    __half* oh = Wth + (size_t)z * DIM * DIM;
    #pragma unroll
    for (int r = ty; r < 32; r += 8)
        oh[(size_t)(n0 + r) * DIM + k0 + tx] = __float2half_rn(t[tx][r]);
}

// ---------------- QK GEMM: Q (2-pass, hi/lo out), K (1-pass, hi out) --------
__global__ __launch_bounds__(256) void qk_gemm() {
    extern __shared__ char smg[];
    const int tid = threadIdx.x;
    const int wid = tid >> 5, lane = tid & 31;
    const int n0 = blockIdx.x * 64, m0 = blockIdx.y * 128, z = blockIdx.z;
    const int wm = (wid & 3) * 32, wn = (wid >> 2) * 32;

    float acc[2][4][4] = {};
    if (z == 0) {
        gemm_tile_db(Xh + (size_t)m0 * DIM, Xl + (size_t)m0 * DIM, DIM,
                     Wth + (size_t)n0 * DIM, DIM, DIM / 64, smg, acc);
        #pragma unroll
        for (int mi = 0; mi < 2; mi++) {
            const int row0 = m0 + wm + mi * 16 + (lane >> 2);
            #pragma unroll
            for (int ni = 0; ni < 4; ni++) {
                const int col = n0 + wn + ni * 8 + (lane & 3) * 2;
                #pragma unroll
                for (int half = 0; half < 2; half++) {
                    const float v0 = acc[mi][ni][half * 2 + 0];
                    const float v1 = acc[mi][ni][half * 2 + 1];
                    const __half h0 = __float2half_rn(v0);
                    const __half h1 = __float2half_rn(v1);
                    const size_t idx = (size_t)(row0 + half * 8) * DIM + col;
                    *(uint32_t*)(Qh + idx) = pack_half2(h0, h1);
                    *(uint32_t*)(Ql + idx) = pack_half2(
                        __float2half_rn(v0 - __half2float(h0)),
                        __float2half_rn(v1 - __half2float(h1)));
                }
            }
        }
    } else {
        gemm_tile_1p(Xh + (size_t)m0 * DIM, DIM,
                     Wth + (size_t)DIM * DIM + (size_t)n0 * DIM, DIM,
                     DIM / 64, smg, acc);
        #pragma unroll
        for (int mi = 0; mi < 2; mi++) {
            const int row0 = m0 + wm + mi * 16 + (lane >> 2);
            #pragma unroll
            for (int ni = 0; ni < 4; ni++) {
                const int col = n0 + wn + ni * 8 + (lane & 3) * 2;
                #pragma unroll
                for (int half = 0; half < 2; half++) {
                    const size_t idx = (size_t)(row0 + half * 8) * DIM + col;
                    *(uint32_t*)(Kh + idx) = pack_half2(
                        __float2half_rn(acc[mi][ni][half * 2 + 0]),
                        __float2half_rn(acc[mi][ni][half * 2 + 1]));
                }
            }
        }
    }
}

// ---------------- fused launch: S = Q@K^T (triangular) + V projection -------
// grid (48, 16, 4): x<32 -> S-tile role; x>=32 -> V-projection role (1-pass).
__global__ __launch_bounds__(256) void sv_gemm() {
    extern __shared__ char smg[];
    const int tid = threadIdx.x;
    const int wid = tid >> 5, lane = tid & 31;
    const int wm = (wid & 3) * 32, wn = (wid >> 2) * 32;

    if (blockIdx.x >= 32) {
        // ---- V projection role (1-pass): vid in [0, 1024) ----
        const int vid = (blockIdx.x - 32) + 16 * (blockIdx.y + 16 * blockIdx.z);
        const int n0 = (vid & 15) * 64;
        const int m0 = (vid >> 4) * 128;

        float acc[2][4][4] = {};
        gemm_tile_1p(Xh + (size_t)m0 * DIM, DIM,
                     Wth + 2 * (size_t)DIM * DIM + (size_t)n0 * DIM, DIM,
                     DIM / 64, smg, acc);

        // transpose 32x32 warp tile via smem, write Vt[b][d][s] (hi only)
        __syncthreads();
        __half* th = (__half*)smg + (size_t)wid * 32 * 34;
        #pragma unroll
        for (int mi = 0; mi < 2; mi++) {
            const int rl = mi * 16 + (lane >> 2);
            #pragma unroll
            for (int ni = 0; ni < 4; ni++) {
                const int cl = ni * 8 + (lane & 3) * 2;
                #pragma unroll
                for (int half = 0; half < 2; half++) {
                    const int r = rl + half * 8;
                    th[(cl + 0) * 34 + r] = __float2half_rn(acc[mi][ni][half * 2 + 0]);
                    th[(cl + 1) * 34 + r] = __float2half_rn(acc[mi][ni][half * 2 + 1]);
                }
            }
        }
        __syncwarp();
        const int b    = m0 >> 11;
        const int sloc = (m0 & (SEQ - 1)) + wm;
        __half* vth = Vth + (size_t)b * DIM * SEQ;
        #pragma unroll 4
        for (int c = 0; c < 32; c++)
            vth[(size_t)(n0 + wn + c) * SEQ + sloc + lane] = th[c * 34 + lane];
        return;
    }

    // ---- S role (triangular, heavy tiles first, scale fused) ----
    const int bn = blockIdx.x;
    const int bm = gridDim.y - 1 - blockIdx.y;
    const int b  = blockIdx.z;
    if (bn > 2 * bm + 1) return;
    const int m0 = bm * 128, n0 = bn * 64;

    const size_t boff = (size_t)b * SEQ * DIM;
    float acc[2][4][4] = {};
    gemm_tile_db(Qh + boff + (size_t)m0 * DIM, Ql + boff + (size_t)m0 * DIM, DIM,
                 Kh + boff + (size_t)n0 * DIM, DIM,
                 DIM / 64, smg, acc);

    float* S = Sg + (size_t)b * SEQ * SEQ;
    const float scale = 0.03125f;
    #pragma unroll
    for (int mi = 0; mi < 2; mi++) {
        const int row0 = m0 + wm + mi * 16 + (lane >> 2);
        #pragma unroll
        for (int ni = 0; ni < 4; ni++) {
            const int col = n0 + wn + ni * 8 + (lane & 3) * 2;
            *(float2*)(S + (size_t)row0 * SEQ + col) =
                make_float2(acc[mi][ni][0] * scale, acc[mi][ni][1] * scale);
            *(float2*)(S + (size_t)(row0 + 8) * SEQ + col) =
                make_float2(acc[mi][ni][2] * scale, acc[mi][ni][3] * scale);
        }
    }
}

// ---------------- softmax + fp16 hi/lo split: Sg -> Ph/Pl --------------------
__global__ __launch_bounds__(256) void softmax_split() {
    __shared__ float4 ebuf4[SEQ / 4];
    __shared__ float red[8];
    const int q = blockIdx.x, b = blockIdx.y;
    const int rowpad4 = (((q >> 7) << 7) + 128) >> 2;
    const int tid = threadIdx.x, wid = tid >> 5, lane = tid & 31;

    const float4* srow4 = (const float4*)(Sg + ((size_t)b * SEQ + q) * SEQ);

    float sum = 0.0f;
    for (int i = tid; i < rowpad4; i += 256) {
        const float4 s4 = srow4[i];
        const int base = i * 4;
        float4 e;
        e.x = (base + 0 <= q) ? __expf(s4.x) : 0.0f;
        e.y = (base + 1 <= q) ? __expf(s4.y) : 0.0f;
        e.z = (base + 2 <= q) ? __expf(s4.z) : 0.0f;
        e.w = (base + 3 <= q) ? __expf(s4.w) : 0.0f;
        ebuf4[i] = e;
        sum += (e.x + e.y) + (e.z + e.w);
    }
    #pragma unroll
    for (int o = 16; o; o >>= 1) sum += __shfl_xor_sync(0xffffffffu, sum, o);
    if (lane == 0) red[wid] = sum;
    __syncthreads();
    float s2 = red[0];
    #pragma unroll
    for (int i = 1; i < 8; i++) s2 += red[i];
    const float inv = 1.0f / s2;

    uint2* ph = (uint2*)(Ph + ((size_t)b * SEQ + q) * SEQ);
    uint2* pl = (uint2*)(Pl + ((size_t)b * SEQ + q) * SEQ);
    for (int i = tid; i < rowpad4; i += 256) {
        const float4 e = ebuf4[i];
        const float p0 = e.x * inv, p1 = e.y * inv, p2 = e.z * inv, p3 = e.w * inv;
        const __half h0 = __float2half_rn(p0);
        const __half h1 = __float2half_rn(p1);
        const __half h2 = __float2half_rn(p2);
        const __half h3 = __float2half_rn(p3);
        ph[i] = make_uint2(pack_half2(h0, h1), pack_half2(h2, h3));
        pl[i] = make_uint2(
            pack_half2(__float2half_rn(p0 - __half2float(h0)),
                       __float2half_rn(p1 - __half2float(h1))),
            pack_half2(__float2half_rn(p2 - __half2float(h2)),
                       __float2half_rn(p3 - __half2float(h3))));
    }
}

// ---------------- O GEMM: out = P @ V (causal k-range) ----------------------
__global__ __launch_bounds__(256) void o_gemm(float* __restrict__ out) {
    extern __shared__ char smg[];
    const int tid = threadIdx.x;
    const int wid = tid >> 5, lane = tid & 31;
    const int bn = blockIdx.x;
    const int bm = gridDim.y - 1 - blockIdx.y;   // heavy rows first
    const int b  = blockIdx.z;
    const int m0 = bm * 128, n0 = bn * 64;
    const int wm = (wid & 3) * 32, wn = (wid >> 2) * 32;

    const size_t poff = (size_t)b * SEQ * SEQ;
    const size_t voff = (size_t)b * DIM * SEQ;
    float acc[2][4][4] = {};
    gemm_tile_db(Ph + poff + (size_t)m0 * SEQ, Pl + poff + (size_t)m0 * SEQ, SEQ,
                 Vth + voff + (size_t)n0 * SEQ, SEQ,
                 (m0 + 128) / 64, smg, acc);

    float* O = out + (size_t)b * SEQ * DIM;
    #pragma unroll
    for (int mi = 0; mi < 2; mi++) {
        const int row0 = m0 + wm + mi * 16 + (lane >> 2);
        #pragma unroll
        for (int ni = 0; ni < 4; ni++) {
            const int col = n0 + wn + ni * 8 + (lane & 3) * 2;
            *(float2*)(O + (size_t)row0 * DIM + col) =
                make_float2(acc[mi][ni][0], acc[mi][ni][1]);
            *(float2*)(O + (size_t)(row0 + 8) * DIM + col) =
                make_float2(acc[mi][ni][2], acc[mi][ni][3]);
        }
    }
}

// ---------------------------------------------------------------------------
extern "C" void kernel_launch(void* const* d_in, const int* in_sizes, int n_in,
                              void* d_out, int out_size)
{
    const float* x  = (const float*)d_in[0];
    const float* Wq = (const float*)d_in[1];
    const float* Wk = (const float*)d_in[2];
    const float* Wv = (const float*)d_in[3];
    float* out = (float*)d_out;

    cudaFuncSetAttribute(qk_gemm, cudaFuncAttributeMaxDynamicSharedMemorySize, GEMM_SMEM);
    cudaFuncSetAttribute(sv_gemm, cudaFuncAttributeMaxDynamicSharedMemorySize, GEMM_SMEM);
    cudaFuncSetAttribute(o_gemm,  cudaFuncAttributeMaxDynamicSharedMemorySize, GEMM_SMEM);

    // fp32 -> fp16 (hi/lo for X, hi-only transposed for W)
    convert_x<<<MTOT * DIM / (256 * 4), 256>>>(x);
    convert_w<<<dim3(DIM / 32, DIM / 32, 3), dim3(32, 8)>>>(Wq, Wk, Wv);

    // Q (2-pass) + K (1-pass) projections
    qk_gemm<<<dim3(DIM / 64, MTOT / 128, 2), 256, GEMM_SMEM>>>();

    // Fused: S scores (triangular, scaled) + V projection (1-pass, transposed)
    sv_gemm<<<dim3(48, 16, BATCH), 256, GEMM_SMEM>>>();

    // Softmax (no max pass) + P fp16 hi/lo split
    softmax_split<<<dim3(SEQ, BATCH), 256>>>();

    // O = P @ V
    o_gemm<<<dim3(DIM / 64, SEQ / 128, BATCH), 256, GEMM_SMEM>>>(out);
}

// round 12
// speedup vs baseline: 2.7002x; 1.2759x over previous
#include <cuda_runtime.h>
#include <cuda_fp16.h>
#include <cstdint>

#define BATCH 4
#define SEQ   2048
#define DIM   1024
#define MTOT  (BATCH*SEQ)

// ------------------------- device scratch (no allocs) -----------------------
__device__ __half Xh[MTOT*(size_t)DIM];
__device__ __half Wth[3*(size_t)DIM*DIM];    // [z][n][k], fp16(W) transposed
__device__ __half Qh[MTOT*(size_t)DIM];      // fp16 only (1-pass path)
__device__ __half Kh[MTOT*(size_t)DIM];
__device__ __half Vth[MTOT*(size_t)DIM];     // [b][d][s]
__device__ float  Sg [(size_t)BATCH*SEQ*SEQ];    // [b][q][k] (pre-scaled)
__device__ __half Ph [(size_t)BATCH*SEQ*SEQ];
__device__ __half Pl [(size_t)BATCH*SEQ*SEQ];

// ------------------------------ helpers -------------------------------------
__device__ __forceinline__ uint32_t smem_to_u32(const void* p) {
    uint32_t a;
    asm("{ .reg .u64 t; cvta.to.shared.u64 t, %1; cvt.u32.u64 %0, t; }"
        : "=r"(a) : "l"(p));
    return a;
}
#define SW128(off) ((off) ^ (((off) >> 3) & 0x70))

__device__ __forceinline__ void ldsm_x4(uint32_t* r, uint32_t addr) {
    asm volatile("ldmatrix.sync.aligned.m8n8.x4.shared.b16 {%0,%1,%2,%3}, [%4];"
                 : "=r"(r[0]), "=r"(r[1]), "=r"(r[2]), "=r"(r[3]) : "r"(addr));
}
__device__ __forceinline__ void mma_f16(float* c, const uint32_t* a, const uint32_t* b) {
    asm volatile(
        "mma.sync.aligned.m16n8k16.row.col.f32.f16.f16.f32 "
        "{%0,%1,%2,%3}, {%4,%5,%6,%7}, {%8,%9}, {%0,%1,%2,%3};"
        : "+f"(c[0]), "+f"(c[1]), "+f"(c[2]), "+f"(c[3])
        : "r"(a[0]), "r"(a[1]), "r"(a[2]), "r"(a[3]), "r"(b[0]), "r"(b[1]));
}
__device__ __forceinline__ void cp16(uint32_t smem_dst, const void* gptr) {
    asm volatile("cp.async.cg.shared.global [%0], [%1], 16;"
                 :: "r"(smem_dst), "l"(gptr));
}
__device__ __forceinline__ uint32_t pack_half2(__half a, __half b) {
    __half2 h2 = __halves2half2(a, b);
    return *(uint32_t*)&h2;
}

// ----------------- double-buffered fp16x2 mainloop (2-pass, o_gemm) ----------
// Block tile 128m x 64n x 64k, 8 warps (warp tile 32x32), cp.async 2-stage.
// C = (Ah + Al) . Bh ; stage (40 KB): Ah[16K] Al[16K] Bh[8K].
#define ST_AH 0
#define ST_AL 16384
#define ST_BH 32768
#define STAGE 40960
#define GEMM_SMEM (2*STAGE)   // 81920

__device__ __forceinline__ void gemm_tile_db(
    const __half* __restrict__ Ahp, const __half* __restrict__ Alp, size_t lda,
    const __half* __restrict__ Bhp, size_t ldb,
    int kIters, char* smem, float acc[2][4][4])
{
    const int tid = threadIdx.x;
    const int wid = tid >> 5, lane = tid & 31;
    const int wm = (wid & 3) * 32;
    const int wn = (wid >> 2) * 32;
    const uint32_t sbase = smem_to_u32(smem);

    const int r8 = tid >> 3, j8 = tid & 7;

    auto issue = [&](int c) {
        const int kc = c * 64;
        const uint32_t st = sbase + (c & 1) * STAGE;
        #pragma unroll
        for (int i = 0; i < 4; i++) {
            const int r = r8 + i * 32;
            const uint32_t off = SW128((uint32_t)(r * 128 + j8 * 16));
            const size_t g = (size_t)r * lda + kc + j8 * 8;
            cp16(st + ST_AH + off, Ahp + g);
            cp16(st + ST_AL + off, Alp + g);
        }
        #pragma unroll
        for (int i = 0; i < 2; i++) {
            const int r = r8 + i * 32;
            const uint32_t off = SW128((uint32_t)(r * 128 + j8 * 16));
            cp16(st + ST_BH + off, Bhp + (size_t)r * ldb + kc + j8 * 8);
        }
        asm volatile("cp.async.commit_group;" ::: "memory");
    };

    const int a_row = (lane & 15);
    const int a_k8  = ((lane >> 4) & 1) * 8;
    const int b_row = (lane & 7) + ((lane >> 4) & 1) * 8;
    const int b_k8  = ((lane >> 3) & 1) * 8;

    issue(0);

    for (int c = 0; c < kIters; c++) {
        if (c + 1 < kIters) {
            issue(c + 1);
            asm volatile("cp.async.wait_group 1;" ::: "memory");
        } else {
            asm volatile("cp.async.wait_group 0;" ::: "memory");
        }
        __syncthreads();

        const uint32_t st = sbase + (c & 1) * STAGE;
        #pragma unroll
        for (int ks = 0; ks < 4; ks++) {
            const int kbase = ks * 16;
            uint32_t ah[2][4], al[2][4];
            #pragma unroll
            for (int mi = 0; mi < 2; mi++) {
                const uint32_t off =
                    SW128((uint32_t)((wm + mi * 16 + a_row) * 128 + (kbase + a_k8) * 2));
                ldsm_x4(ah[mi], st + ST_AH + off);
                ldsm_x4(al[mi], st + ST_AL + off);
            }
            uint32_t bh[4][2];
            #pragma unroll
            for (int p = 0; p < 2; p++) {
                const uint32_t off =
                    SW128((uint32_t)((wn + p * 16 + b_row) * 128 + (kbase + b_k8) * 2));
                uint32_t t[4];
                ldsm_x4(t, st + ST_BH + off);
                bh[2 * p][0] = t[0]; bh[2 * p][1] = t[1];
                bh[2 * p + 1][0] = t[2]; bh[2 * p + 1][1] = t[3];
            }
            #pragma unroll
            for (int mi = 0; mi < 2; mi++)
                #pragma unroll
                for (int ni = 0; ni < 4; ni++) {
                    mma_f16(acc[mi][ni], ah[mi], bh[ni]);
                    mma_f16(acc[mi][ni], al[mi], bh[ni]);
                }
        }
        __syncthreads();
    }
}

// ----------------- 1-pass variant: C = Ah . Bh ------------------------------
// Stage (24 KB): Ah[16K] Bh[8K]. 48 KB total -> 3 CTAs/SM.
#define ST1_BH 16384
#define STAGE1 24576
#define GEMM1_SMEM (2*STAGE1)   // 49152

__device__ __forceinline__ void gemm_tile_1p(
    const __half* __restrict__ Ahp, size_t lda,
    const __half* __restrict__ Bhp, size_t ldb,
    int kIters, char* smem, float acc[2][4][4])
{
    const int tid = threadIdx.x;
    const int wid = tid >> 5, lane = tid & 31;
    const int wm = (wid & 3) * 32;
    const int wn = (wid >> 2) * 32;
    const uint32_t sbase = smem_to_u32(smem);

    const int r8 = tid >> 3, j8 = tid & 7;

    auto issue = [&](int c) {
        const int kc = c * 64;
        const uint32_t st = sbase + (c & 1) * STAGE1;
        #pragma unroll
        for (int i = 0; i < 4; i++) {
            const int r = r8 + i * 32;
            const uint32_t off = SW128((uint32_t)(r * 128 + j8 * 16));
            cp16(st + off, Ahp + (size_t)r * lda + kc + j8 * 8);
        }
        #pragma unroll
        for (int i = 0; i < 2; i++) {
            const int r = r8 + i * 32;
            const uint32_t off = SW128((uint32_t)(r * 128 + j8 * 16));
            cp16(st + ST1_BH + off, Bhp + (size_t)r * ldb + kc + j8 * 8);
        }
        asm volatile("cp.async.commit_group;" ::: "memory");
    };

    const int a_row = (lane & 15);
    const int a_k8  = ((lane >> 4) & 1) * 8;
    const int b_row = (lane & 7) + ((lane >> 4) & 1) * 8;
    const int b_k8  = ((lane >> 3) & 1) * 8;

    issue(0);

    for (int c = 0; c < kIters; c++) {
        if (c + 1 < kIters) {
            issue(c + 1);
            asm volatile("cp.async.wait_group 1;" ::: "memory");
        } else {
            asm volatile("cp.async.wait_group 0;" ::: "memory");
        }
        __syncthreads();

        const uint32_t st = sbase + (c & 1) * STAGE1;
        #pragma unroll
        for (int ks = 0; ks < 4; ks++) {
            const int kbase = ks * 16;
            uint32_t ah[2][4];
            #pragma unroll
            for (int mi = 0; mi < 2; mi++) {
                const uint32_t off =
                    SW128((uint32_t)((wm + mi * 16 + a_row) * 128 + (kbase + a_k8) * 2));
                ldsm_x4(ah[mi], st + off);
            }
            uint32_t bh[4][2];
            #pragma unroll
            for (int p = 0; p < 2; p++) {
                const uint32_t off =
                    SW128((uint32_t)((wn + p * 16 + b_row) * 128 + (kbase + b_k8) * 2));
                uint32_t t[4];
                ldsm_x4(t, st + ST1_BH + off);
                bh[2 * p][0] = t[0]; bh[2 * p][1] = t[1];
                bh[2 * p + 1][0] = t[2]; bh[2 * p + 1][1] = t[3];
            }
            #pragma unroll
            for (int mi = 0; mi < 2; mi++)
                #pragma unroll
                for (int ni = 0; ni < 4; ni++)
                    mma_f16(acc[mi][ni], ah[mi], bh[ni]);
        }
        __syncthreads();
    }
}

// --------------------------- conversion kernels -----------------------------
__global__ __launch_bounds__(256) void convert_x(const float* __restrict__ x) {
    size_t i = ((size_t)blockIdx.x * 256 + threadIdx.x) * 4;
    float4 v = *(const float4*)(x + i);
    *(uint32_t*)(Xh + i)     = pack_half2(__float2half_rn(v.x), __float2half_rn(v.y));
    *(uint32_t*)(Xh + i + 2) = pack_half2(__float2half_rn(v.z), __float2half_rn(v.w));
}

// Transpose W, hi only: Wth[z][n][k] = fp16(W[z][k][n])
__global__ void convert_w(const float* __restrict__ Wq,
                          const float* __restrict__ Wk,
                          const float* __restrict__ Wv) {
    __shared__ float t[32][33];
    const int z = blockIdx.z;
    const float* W = (z == 0) ? Wq : ((z == 1) ? Wk : Wv);
    const int n0 = blockIdx.x * 32, k0 = blockIdx.y * 32;
    const int tx = threadIdx.x, ty = threadIdx.y;
    #pragma unroll
    for (int r = ty; r < 32; r += 8)
        t[r][tx] = W[(size_t)(k0 + r) * DIM + n0 + tx];
    __syncthreads();
    __half* oh = Wth + (size_t)z * DIM * DIM;
    #pragma unroll
    for (int r = ty; r < 32; r += 8)
        oh[(size_t)(n0 + r) * DIM + k0 + tx] = __float2half_rn(t[tx][r]);
}

// ---------------- QK GEMM: Q and K projections, both 1-pass -----------------
__global__ __launch_bounds__(256) void qk_gemm() {
    extern __shared__ char smg[];
    const int tid = threadIdx.x;
    const int wid = tid >> 5, lane = tid & 31;
    const int n0 = blockIdx.x * 64, m0 = blockIdx.y * 128, z = blockIdx.z;
    const int wm = (wid & 3) * 32, wn = (wid >> 2) * 32;

    float acc[2][4][4] = {};
    gemm_tile_1p(Xh + (size_t)m0 * DIM, DIM,
                 Wth + (size_t)z * DIM * DIM + (size_t)n0 * DIM, DIM,
                 DIM / 64, smg, acc);

    __half* D = (z == 0) ? Qh : Kh;
    #pragma unroll
    for (int mi = 0; mi < 2; mi++) {
        const int row0 = m0 + wm + mi * 16 + (lane >> 2);
        #pragma unroll
        for (int ni = 0; ni < 4; ni++) {
            const int col = n0 + wn + ni * 8 + (lane & 3) * 2;
            #pragma unroll
            for (int half = 0; half < 2; half++) {
                const size_t idx = (size_t)(row0 + half * 8) * DIM + col;
                *(uint32_t*)(D + idx) = pack_half2(
                    __float2half_rn(acc[mi][ni][half * 2 + 0]),
                    __float2half_rn(acc[mi][ni][half * 2 + 1]));
            }
        }
    }
}

// ---------------- fused launch: S = Qh@Kh^T (triangular) + V projection -----
// grid (48, 16, 4): x<32 -> S-tile role; x>=32 -> V-projection role. All 1-pass.
__global__ __launch_bounds__(256) void sv_gemm() {
    extern __shared__ char smg[];
    const int tid = threadIdx.x;
    const int wid = tid >> 5, lane = tid & 31;
    const int wm = (wid & 3) * 32, wn = (wid >> 2) * 32;

    if (blockIdx.x >= 32) {
        // ---- V projection role (1-pass): vid in [0, 1024) ----
        const int vid = (blockIdx.x - 32) + 16 * (blockIdx.y + 16 * blockIdx.z);
        const int n0 = (vid & 15) * 64;
        const int m0 = (vid >> 4) * 128;

        float acc[2][4][4] = {};
        gemm_tile_1p(Xh + (size_t)m0 * DIM, DIM,
                     Wth + 2 * (size_t)DIM * DIM + (size_t)n0 * DIM, DIM,
                     DIM / 64, smg, acc);

        // transpose 32x32 warp tile via smem, write Vt[b][d][s]
        __syncthreads();
        __half* th = (__half*)smg + (size_t)wid * 32 * 34;
        #pragma unroll
        for (int mi = 0; mi < 2; mi++) {
            const int rl = mi * 16 + (lane >> 2);
            #pragma unroll
            for (int ni = 0; ni < 4; ni++) {
                const int cl = ni * 8 + (lane & 3) * 2;
                #pragma unroll
                for (int half = 0; half < 2; half++) {
                    const int r = rl + half * 8;
                    th[(cl + 0) * 34 + r] = __float2half_rn(acc[mi][ni][half * 2 + 0]);
                    th[(cl + 1) * 34 + r] = __float2half_rn(acc[mi][ni][half * 2 + 1]);
                }
            }
        }
        __syncwarp();
        const int b    = m0 >> 11;
        const int sloc = (m0 & (SEQ - 1)) + wm;
        __half* vth = Vth + (size_t)b * DIM * SEQ;
        #pragma unroll 4
        for (int c = 0; c < 32; c++)
            vth[(size_t)(n0 + wn + c) * SEQ + sloc + lane] = th[c * 34 + lane];
        return;
    }

    // ---- S role (triangular, heavy tiles first, scale fused, 1-pass) ----
    const int bn = blockIdx.x;
    const int bm = gridDim.y - 1 - blockIdx.y;
    const int b  = blockIdx.z;
    if (bn > 2 * bm + 1) return;
    const int m0 = bm * 128, n0 = bn * 64;

    const size_t boff = (size_t)b * SEQ * DIM;
    float acc[2][4][4] = {};
    gemm_tile_1p(Qh + boff + (size_t)m0 * DIM, DIM,
                 Kh + boff + (size_t)n0 * DIM, DIM,
                 DIM / 64, smg, acc);

    float* S = Sg + (size_t)b * SEQ * SEQ;
    const float scale = 0.03125f;
    #pragma unroll
    for (int mi = 0; mi < 2; mi++) {
        const int row0 = m0 + wm + mi * 16 + (lane >> 2);
        #pragma unroll
        for (int ni = 0; ni < 4; ni++) {
            const int col = n0 + wn + ni * 8 + (lane & 3) * 2;
            *(float2*)(S + (size_t)row0 * SEQ + col) =
                make_float2(acc[mi][ni][0] * scale, acc[mi][ni][1] * scale);
            *(float2*)(S + (size_t)(row0 + 8) * SEQ + col) =
                make_float2(acc[mi][ni][2] * scale, acc[mi][ni][3] * scale);
        }
    }
}

// ---------------- softmax + fp16 hi/lo split: Sg -> Ph/Pl --------------------
__global__ __launch_bounds__(256) void softmax_split() {
    __shared__ float4 ebuf4[SEQ / 4];
    __shared__ float red[8];
    const int q = blockIdx.x, b = blockIdx.y;
    const int rowpad4 = (((q >> 7) << 7) + 128) >> 2;
    const int tid = threadIdx.x, wid = tid >> 5, lane = tid & 31;

    const float4* srow4 = (const float4*)(Sg + ((size_t)b * SEQ + q) * SEQ);

    float sum = 0.0f;
    for (int i = tid; i < rowpad4; i += 256) {
        const float4 s4 = srow4[i];
        const int base = i * 4;
        float4 e;
        e.x = (base + 0 <= q) ? __expf(s4.x) : 0.0f;
        e.y = (base + 1 <= q) ? __expf(s4.y) : 0.0f;
        e.z = (base + 2 <= q) ? __expf(s4.z) : 0.0f;
        e.w = (base + 3 <= q) ? __expf(s4.w) : 0.0f;
        ebuf4[i] = e;
        sum += (e.x + e.y) + (e.z + e.w);
    }
    #pragma unroll
    for (int o = 16; o; o >>= 1) sum += __shfl_xor_sync(0xffffffffu, sum, o);
    if (lane == 0) red[wid] = sum;
    __syncthreads();
    float s2 = red[0];
    #pragma unroll
    for (int i = 1; i < 8; i++) s2 += red[i];
    const float inv = 1.0f / s2;

    uint2* ph = (uint2*)(Ph + ((size_t)b * SEQ + q) * SEQ);
    uint2* pl = (uint2*)(Pl + ((size_t)b * SEQ + q) * SEQ);
    for (int i = tid; i < rowpad4; i += 256) {
        const float4 e = ebuf4[i];
        const float p0 = e.x * inv, p1 = e.y * inv, p2 = e.z * inv, p3 = e.w * inv;
        const __half h0 = __float2half_rn(p0);
        const __half h1 = __float2half_rn(p1);
        const __half h2 = __float2half_rn(p2);
        const __half h3 = __float2half_rn(p3);
        ph[i] = make_uint2(pack_half2(h0, h1), pack_half2(h2, h3));
        pl[i] = make_uint2(
            pack_half2(__float2half_rn(p0 - __half2float(h0)),
                       __float2half_rn(p1 - __half2float(h1))),
            pack_half2(__float2half_rn(p2 - __half2float(h2)),
                       __float2half_rn(p3 - __half2float(h3))));
    }
}

// ---------------- O GEMM: out = P @ V (2-pass, causal k-range) --------------
__global__ __launch_bounds__(256) void o_gemm(float* __restrict__ out) {
    extern __shared__ char smg[];
    const int tid = threadIdx.x;
    const int wid = tid >> 5, lane = tid & 31;
    const int bn = blockIdx.x;
    const int bm = gridDim.y - 1 - blockIdx.y;   // heavy rows first
    const int b  = blockIdx.z;
    const int m0 = bm * 128, n0 = bn * 64;
    const int wm = (wid & 3) * 32, wn = (wid >> 2) * 32;

    const size_t poff = (size_t)b * SEQ * SEQ;
    const size_t voff = (size_t)b * DIM * SEQ;
    float acc[2][4][4] = {};
    gemm_tile_db(Ph + poff + (size_t)m0 * SEQ, Pl + poff + (size_t)m0 * SEQ, SEQ,
                 Vth + voff + (size_t)n0 * SEQ, SEQ,
                 (m0 + 128) / 64, smg, acc);

    float* O = out + (size_t)b * SEQ * DIM;
    #pragma unroll
    for (int mi = 0; mi < 2; mi++) {
        const int row0 = m0 + wm + mi * 16 + (lane >> 2);
        #pragma unroll
        for (int ni = 0; ni < 4; ni++) {
            const int col = n0 + wn + ni * 8 + (lane & 3) * 2;
            *(float2*)(O + (size_t)row0 * DIM + col) =
                make_float2(acc[mi][ni][0], acc[mi][ni][1]);
            *(float2*)(O + (size_t)(row0 + 8) * DIM + col) =
                make_float2(acc[mi][ni][2], acc[mi][ni][3]);
        }
    }
}

// ---------------------------------------------------------------------------
extern "C" void kernel_launch(void* const* d_in, const int* in_sizes, int n_in,
                              void* d_out, int out_size)
{
    const float* x  = (const float*)d_in[0];
    const float* Wq = (const float*)d_in[1];
    const float* Wk = (const float*)d_in[2];
    const float* Wv = (const float*)d_in[3];
    float* out = (float*)d_out;

    cudaFuncSetAttribute(qk_gemm, cudaFuncAttributeMaxDynamicSharedMemorySize, GEMM1_SMEM);
    cudaFuncSetAttribute(sv_gemm, cudaFuncAttributeMaxDynamicSharedMemorySize, GEMM1_SMEM);
    cudaFuncSetAttribute(o_gemm,  cudaFuncAttributeMaxDynamicSharedMemorySize, GEMM_SMEM);

    // fp32 -> fp16 (hi only now)
    convert_x<<<MTOT * DIM / (256 * 4), 256>>>(x);
    convert_w<<<dim3(DIM / 32, DIM / 32, 3), dim3(32, 8)>>>(Wq, Wk, Wv);

    // Q + K projections (1-pass, 3 CTAs/SM)
    qk_gemm<<<dim3(DIM / 64, MTOT / 128, 2), 256, GEMM1_SMEM>>>();

    // Fused: S scores (1-pass, triangular, scaled) + V projection (1-pass)
    sv_gemm<<<dim3(48, 16, BATCH), 256, GEMM1_SMEM>>>();

    // Softmax (no max pass) + P fp16 hi/lo split
    softmax_split<<<dim3(SEQ, BATCH), 256>>>();

    // O = P @ V (2-pass)
    o_gemm<<<dim3(DIM / 64, SEQ / 128, BATCH), 256, GEMM_SMEM>>>(out);
}

// round 13
// speedup vs baseline: 3.0032x; 1.1122x over previous
#include <cuda_runtime.h>
#include <cuda_fp16.h>
#include <cstdint>

#define BATCH 4
#define SEQ   2048
#define DIM   1024
#define MTOT  (BATCH*SEQ)

// ------------------------- device scratch (no allocs) -----------------------
__device__ __half Xh[MTOT*(size_t)DIM];
__device__ __half Wth[3*(size_t)DIM*DIM];    // [z][n][k], fp16(W) transposed
__device__ __half Qh[MTOT*(size_t)DIM];
__device__ __half Kh[MTOT*(size_t)DIM];
__device__ __half Vth[MTOT*(size_t)DIM];     // [b][d][s]
__device__ float  Sg [(size_t)BATCH*SEQ*SEQ];    // [b][q][k] (pre-scaled)
__device__ __half Ph [(size_t)BATCH*SEQ*SEQ];

// ------------------------------ helpers -------------------------------------
__device__ __forceinline__ uint32_t smem_to_u32(const void* p) {
    uint32_t a;
    asm("{ .reg .u64 t; cvta.to.shared.u64 t, %1; cvt.u32.u64 %0, t; }"
        : "=r"(a) : "l"(p));
    return a;
}
#define SW128(off) ((off) ^ (((off) >> 3) & 0x70))

__device__ __forceinline__ void ldsm_x4(uint32_t* r, uint32_t addr) {
    asm volatile("ldmatrix.sync.aligned.m8n8.x4.shared.b16 {%0,%1,%2,%3}, [%4];"
                 : "=r"(r[0]), "=r"(r[1]), "=r"(r[2]), "=r"(r[3]) : "r"(addr));
}
__device__ __forceinline__ void mma_f16(float* c, const uint32_t* a, const uint32_t* b) {
    asm volatile(
        "mma.sync.aligned.m16n8k16.row.col.f32.f16.f16.f32 "
        "{%0,%1,%2,%3}, {%4,%5,%6,%7}, {%8,%9}, {%0,%1,%2,%3};"
        : "+f"(c[0]), "+f"(c[1]), "+f"(c[2]), "+f"(c[3])
        : "r"(a[0]), "r"(a[1]), "r"(a[2]), "r"(a[3]), "r"(b[0]), "r"(b[1]));
}
__device__ __forceinline__ void cp16(uint32_t smem_dst, const void* gptr) {
    asm volatile("cp.async.cg.shared.global [%0], [%1], 16;"
                 :: "r"(smem_dst), "l"(gptr));
}
__device__ __forceinline__ uint32_t pack_half2(__half a, __half b) {
    __half2 h2 = __halves2half2(a, b);
    return *(uint32_t*)&h2;
}

// ----------------- 1-pass fp16 mainloop: C = Ah . Bh (proven) ----------------
// Block tile 128m x 64n x 64k, 8 warps (warp tile 32x32), cp.async 2-stage.
// Stage (24 KB): Ah[16K] Bh[8K]. 48 KB total -> 3 CTAs/SM.
#define ST1_BH 16384
#define STAGE1 24576
#define GEMM1_SMEM (2*STAGE1)   // 49152

__device__ __forceinline__ void gemm_tile_1p(
    const __half* __restrict__ Ahp, size_t lda,
    const __half* __restrict__ Bhp, size_t ldb,
    int kIters, char* smem, float acc[2][4][4])
{
    const int tid = threadIdx.x;
    const int wid = tid >> 5, lane = tid & 31;
    const int wm = (wid & 3) * 32;
    const int wn = (wid >> 2) * 32;
    const uint32_t sbase = smem_to_u32(smem);

    const int r8 = tid >> 3, j8 = tid & 7;

    auto issue = [&](int c) {
        const int kc = c * 64;
        const uint32_t st = sbase + (c & 1) * STAGE1;
        #pragma unroll
        for (int i = 0; i < 4; i++) {
            const int r = r8 + i * 32;
            const uint32_t off = SW128((uint32_t)(r * 128 + j8 * 16));
            cp16(st + off, Ahp + (size_t)r * lda + kc + j8 * 8);
        }
        #pragma unroll
        for (int i = 0; i < 2; i++) {
            const int r = r8 + i * 32;
            const uint32_t off = SW128((uint32_t)(r * 128 + j8 * 16));
            cp16(st + ST1_BH + off, Bhp + (size_t)r * ldb + kc + j8 * 8);
        }
        asm volatile("cp.async.commit_group;" ::: "memory");
    };

    const int a_row = (lane & 15);
    const int a_k8  = ((lane >> 4) & 1) * 8;
    const int b_row = (lane & 7) + ((lane >> 4) & 1) * 8;
    const int b_k8  = ((lane >> 3) & 1) * 8;

    issue(0);

    for (int c = 0; c < kIters; c++) {
        if (c + 1 < kIters) {
            issue(c + 1);
            asm volatile("cp.async.wait_group 1;" ::: "memory");
        } else {
            asm volatile("cp.async.wait_group 0;" ::: "memory");
        }
        __syncthreads();

        const uint32_t st = sbase + (c & 1) * STAGE1;
        #pragma unroll
        for (int ks = 0; ks < 4; ks++) {
            const int kbase = ks * 16;
            uint32_t ah[2][4];
            #pragma unroll
            for (int mi = 0; mi < 2; mi++) {
                const uint32_t off =
                    SW128((uint32_t)((wm + mi * 16 + a_row) * 128 + (kbase + a_k8) * 2));
                ldsm_x4(ah[mi], st + off);
            }
            uint32_t bh[4][2];
            #pragma unroll
            for (int p = 0; p < 2; p++) {
                const uint32_t off =
                    SW128((uint32_t)((wn + p * 16 + b_row) * 128 + (kbase + b_k8) * 2));
                uint32_t t[4];
                ldsm_x4(t, st + ST1_BH + off);
                bh[2 * p][0] = t[0]; bh[2 * p][1] = t[1];
                bh[2 * p + 1][0] = t[2]; bh[2 * p + 1][1] = t[3];
            }
            #pragma unroll
            for (int mi = 0; mi < 2; mi++)
                #pragma unroll
                for (int ni = 0; ni < 4; ni++)
                    mma_f16(acc[mi][ni], ah[mi], bh[ni]);
        }
        __syncthreads();
    }
}

// --------------------------- conversion kernels -----------------------------
__global__ __launch_bounds__(256) void convert_x(const float* __restrict__ x) {
    size_t i = ((size_t)blockIdx.x * 256 + threadIdx.x) * 4;
    float4 v = *(const float4*)(x + i);
    *(uint32_t*)(Xh + i)     = pack_half2(__float2half_rn(v.x), __float2half_rn(v.y));
    *(uint32_t*)(Xh + i + 2) = pack_half2(__float2half_rn(v.z), __float2half_rn(v.w));
}

// Transpose W: Wth[z][n][k] = fp16(W[z][k][n])
__global__ void convert_w(const float* __restrict__ Wq,
                          const float* __restrict__ Wk,
                          const float* __restrict__ Wv) {
    __shared__ float t[32][33];
    const int z = blockIdx.z;
    const float* W = (z == 0) ? Wq : ((z == 1) ? Wk : Wv);
    const int n0 = blockIdx.x * 32, k0 = blockIdx.y * 32;
    const int tx = threadIdx.x, ty = threadIdx.y;
    #pragma unroll
    for (int r = ty; r < 32; r += 8)
        t[r][tx] = W[(size_t)(k0 + r) * DIM + n0 + tx];
    __syncthreads();
    __half* oh = Wth + (size_t)z * DIM * DIM;
    #pragma unroll
    for (int r = ty; r < 32; r += 8)
        oh[(size_t)(n0 + r) * DIM + k0 + tx] = __float2half_rn(t[tx][r]);
}

// ---------------- QK GEMM: Q and K projections (1-pass) ----------------------
__global__ __launch_bounds__(256) void qk_gemm() {
    extern __shared__ char smg[];
    const int tid = threadIdx.x;
    const int wid = tid >> 5, lane = tid & 31;
    const int n0 = blockIdx.x * 64, m0 = blockIdx.y * 128, z = blockIdx.z;
    const int wm = (wid & 3) * 32, wn = (wid >> 2) * 32;

    float acc[2][4][4] = {};
    gemm_tile_1p(Xh + (size_t)m0 * DIM, DIM,
                 Wth + (size_t)z * DIM * DIM + (size_t)n0 * DIM, DIM,
                 DIM / 64, smg, acc);

    __half* D = (z == 0) ? Qh : Kh;
    #pragma unroll
    for (int mi = 0; mi < 2; mi++) {
        const int row0 = m0 + wm + mi * 16 + (lane >> 2);
        #pragma unroll
        for (int ni = 0; ni < 4; ni++) {
            const int col = n0 + wn + ni * 8 + (lane & 3) * 2;
            #pragma unroll
            for (int half = 0; half < 2; half++) {
                const size_t idx = (size_t)(row0 + half * 8) * DIM + col;
                *(uint32_t*)(D + idx) = pack_half2(
                    __float2half_rn(acc[mi][ni][half * 2 + 0]),
                    __float2half_rn(acc[mi][ni][half * 2 + 1]));
            }
        }
    }
}

// ---------------- fused launch: S = Qh@Kh^T (triangular) + V projection -----
// grid (48, 16, 4): x<32 -> S-tile role; x>=32 -> V-projection role.
__global__ __launch_bounds__(256) void sv_gemm() {
    extern __shared__ char smg[];
    const int tid = threadIdx.x;
    const int wid = tid >> 5, lane = tid & 31;
    const int wm = (wid & 3) * 32, wn = (wid >> 2) * 32;

    if (blockIdx.x >= 32) {
        // ---- V projection role: vid in [0, 1024) ----
        const int vid = (blockIdx.x - 32) + 16 * (blockIdx.y + 16 * blockIdx.z);
        const int n0 = (vid & 15) * 64;
        const int m0 = (vid >> 4) * 128;

        float acc[2][4][4] = {};
        gemm_tile_1p(Xh + (size_t)m0 * DIM, DIM,
                     Wth + 2 * (size_t)DIM * DIM + (size_t)n0 * DIM, DIM,
                     DIM / 64, smg, acc);

        // transpose 32x32 warp tile via smem, write Vt[b][d][s]
        __syncthreads();
        __half* th = (__half*)smg + (size_t)wid * 32 * 34;
        #pragma unroll
        for (int mi = 0; mi < 2; mi++) {
            const int rl = mi * 16 + (lane >> 2);
            #pragma unroll
            for (int ni = 0; ni < 4; ni++) {
                const int cl = ni * 8 + (lane & 3) * 2;
                #pragma unroll
                for (int half = 0; half < 2; half++) {
                    const int r = rl + half * 8;
                    th[(cl + 0) * 34 + r] = __float2half_rn(acc[mi][ni][half * 2 + 0]);
                    th[(cl + 1) * 34 + r] = __float2half_rn(acc[mi][ni][half * 2 + 1]);
                }
            }
        }
        __syncwarp();
        const int b    = m0 >> 11;
        const int sloc = (m0 & (SEQ - 1)) + wm;
        __half* vth = Vth + (size_t)b * DIM * SEQ;
        #pragma unroll 4
        for (int c = 0; c < 32; c++)
            vth[(size_t)(n0 + wn + c) * SEQ + sloc + lane] = th[c * 34 + lane];
        return;
    }

    // ---- S role (triangular, heavy tiles first, scale fused) ----
    const int bn = blockIdx.x;
    const int bm = gridDim.y - 1 - blockIdx.y;
    const int b  = blockIdx.z;
    if (bn > 2 * bm + 1) return;
    const int m0 = bm * 128, n0 = bn * 64;

    const size_t boff = (size_t)b * SEQ * DIM;
    float acc[2][4][4] = {};
    gemm_tile_1p(Qh + boff + (size_t)m0 * DIM, DIM,
                 Kh + boff + (size_t)n0 * DIM, DIM,
                 DIM / 64, smg, acc);

    float* S = Sg + (size_t)b * SEQ * SEQ;
    const float scale = 0.03125f;
    #pragma unroll
    for (int mi = 0; mi < 2; mi++) {
        const int row0 = m0 + wm + mi * 16 + (lane >> 2);
        #pragma unroll
        for (int ni = 0; ni < 4; ni++) {
            const int col = n0 + wn + ni * 8 + (lane & 3) * 2;
            *(float2*)(S + (size_t)row0 * SEQ + col) =
                make_float2(acc[mi][ni][0] * scale, acc[mi][ni][1] * scale);
            *(float2*)(S + (size_t)(row0 + 8) * SEQ + col) =
                make_float2(acc[mi][ni][2] * scale, acc[mi][ni][3] * scale);
        }
    }
}

// ---------------- softmax: Sg -> Ph (fp16 only) ------------------------------
// No max pass: scores are pre-scaled and bounded (|s| <= ~34), exp() is safe.
__global__ __launch_bounds__(256) void softmax_split() {
    __shared__ float4 ebuf4[SEQ / 4];
    __shared__ float red[8];
    const int q = blockIdx.x, b = blockIdx.y;
    const int rowpad4 = (((q >> 7) << 7) + 128) >> 2;
    const int tid = threadIdx.x, wid = tid >> 5, lane = tid & 31;

    const float4* srow4 = (const float4*)(Sg + ((size_t)b * SEQ + q) * SEQ);

    float sum = 0.0f;
    for (int i = tid; i < rowpad4; i += 256) {
        const float4 s4 = srow4[i];
        const int base = i * 4;
        float4 e;
        e.x = (base + 0 <= q) ? __expf(s4.x) : 0.0f;
        e.y = (base + 1 <= q) ? __expf(s4.y) : 0.0f;
        e.z = (base + 2 <= q) ? __expf(s4.z) : 0.0f;
        e.w = (base + 3 <= q) ? __expf(s4.w) : 0.0f;
        ebuf4[i] = e;
        sum += (e.x + e.y) + (e.z + e.w);
    }
    #pragma unroll
    for (int o = 16; o; o >>= 1) sum += __shfl_xor_sync(0xffffffffu, sum, o);
    if (lane == 0) red[wid] = sum;
    __syncthreads();
    float s2 = red[0];
    #pragma unroll
    for (int i = 1; i < 8; i++) s2 += red[i];
    const float inv = 1.0f / s2;

    uint2* ph = (uint2*)(Ph + ((size_t)b * SEQ + q) * SEQ);
    for (int i = tid; i < rowpad4; i += 256) {
        const float4 e = ebuf4[i];
        ph[i] = make_uint2(
            pack_half2(__float2half_rn(e.x * inv), __float2half_rn(e.y * inv)),
            pack_half2(__float2half_rn(e.z * inv), __float2half_rn(e.w * inv)));
    }
}

// ---------------- O GEMM: out = Ph @ V (1-pass, causal k-range) --------------
__global__ __launch_bounds__(256) void o_gemm(float* __restrict__ out) {
    extern __shared__ char smg[];
    const int tid = threadIdx.x;
    const int wid = tid >> 5, lane = tid & 31;
    const int bn = blockIdx.x;
    const int bm = gridDim.y - 1 - blockIdx.y;   // heavy rows first
    const int b  = blockIdx.z;
    const int m0 = bm * 128, n0 = bn * 64;
    const int wm = (wid & 3) * 32, wn = (wid >> 2) * 32;

    const size_t poff = (size_t)b * SEQ * SEQ;
    const size_t voff = (size_t)b * DIM * SEQ;
    float acc[2][4][4] = {};
    gemm_tile_1p(Ph + poff + (size_t)m0 * SEQ, SEQ,
                 Vth + voff + (size_t)n0 * SEQ, SEQ,
                 (m0 + 128) / 64, smg, acc);

    float* O = out + (size_t)b * SEQ * DIM;
    #pragma unroll
    for (int mi = 0; mi < 2; mi++) {
        const int row0 = m0 + wm + mi * 16 + (lane >> 2);
        #pragma unroll
        for (int ni = 0; ni < 4; ni++) {
            const int col = n0 + wn + ni * 8 + (lane & 3) * 2;
            *(float2*)(O + (size_t)row0 * DIM + col) =
                make_float2(acc[mi][ni][0], acc[mi][ni][1]);
            *(float2*)(O + (size_t)(row0 + 8) * DIM + col) =
                make_float2(acc[mi][ni][2], acc[mi][ni][3]);
        }
    }
}

// ---------------------------------------------------------------------------
extern "C" void kernel_launch(void* const* d_in, const int* in_sizes, int n_in,
                              void* d_out, int out_size)
{
    const float* x  = (const float*)d_in[0];
    const float* Wq = (const float*)d_in[1];
    const float* Wk = (const float*)d_in[2];
    const float* Wv = (const float*)d_in[3];
    float* out = (float*)d_out;

    cudaFuncSetAttribute(qk_gemm, cudaFuncAttributeMaxDynamicSharedMemorySize, GEMM1_SMEM);
    cudaFuncSetAttribute(sv_gemm, cudaFuncAttributeMaxDynamicSharedMemorySize, GEMM1_SMEM);
    cudaFuncSetAttribute(o_gemm,  cudaFuncAttributeMaxDynamicSharedMemorySize, GEMM1_SMEM);

    // fp32 -> fp16
    convert_x<<<MTOT * DIM / (256 * 4), 256>>>(x);
    convert_w<<<dim3(DIM / 32, DIM / 32, 3), dim3(32, 8)>>>(Wq, Wk, Wv);

    // Q + K projections (1-pass, 3 CTAs/SM)
    qk_gemm<<<dim3(DIM / 64, MTOT / 128, 2), 256, GEMM1_SMEM>>>();

    // Fused: S scores (triangular, scaled) + V projection
    sv_gemm<<<dim3(48, 16, BATCH), 256, GEMM1_SMEM>>>();

    // Softmax (no max pass) -> Ph
    softmax_split<<<dim3(SEQ, BATCH), 256>>>();

    // O = Ph @ V (1-pass)
    o_gemm<<<dim3(DIM / 64, SEQ / 128, BATCH), 256, GEMM1_SMEM>>>(out);
}

// round 14
// speedup vs baseline: 3.2098x; 1.0688x over previous
#include <cuda_runtime.h>
#include <cuda_fp16.h>
#include <cstdint>

#define BATCH 4
#define SEQ   2048
#define DIM   1024
#define MTOT  (BATCH*SEQ)

// ------------------------- device scratch (no allocs) -----------------------
__device__ __half Xh[MTOT*(size_t)DIM];
__device__ __half Wth[3*(size_t)DIM*DIM];    // [z][n][k], fp16(W) transposed
__device__ __half Qh[MTOT*(size_t)DIM];
__device__ __half Kh[MTOT*(size_t)DIM];
__device__ __half Vth[MTOT*(size_t)DIM];     // [b][d][s]
__device__ float  Sg [(size_t)BATCH*SEQ*SEQ];    // [b][q][k] (pre-scaled)
__device__ __half Ph [(size_t)BATCH*SEQ*SEQ];

// ------------------------------ helpers -------------------------------------
__device__ __forceinline__ uint32_t smem_to_u32(const void* p) {
    uint32_t a;
    asm("{ .reg .u64 t; cvta.to.shared.u64 t, %1; cvt.u32.u64 %0, t; }"
        : "=r"(a) : "l"(p));
    return a;
}
#define SW128(off) ((off) ^ (((off) >> 3) & 0x70))

__device__ __forceinline__ void ldsm_x4(uint32_t* r, uint32_t addr) {
    asm volatile("ldmatrix.sync.aligned.m8n8.x4.shared.b16 {%0,%1,%2,%3}, [%4];"
                 : "=r"(r[0]), "=r"(r[1]), "=r"(r[2]), "=r"(r[3]) : "r"(addr));
}
__device__ __forceinline__ void mma_f16(float* c, const uint32_t* a, const uint32_t* b) {
    asm volatile(
        "mma.sync.aligned.m16n8k16.row.col.f32.f16.f16.f32 "
        "{%0,%1,%2,%3}, {%4,%5,%6,%7}, {%8,%9}, {%0,%1,%2,%3};"
        : "+f"(c[0]), "+f"(c[1]), "+f"(c[2]), "+f"(c[3])
        : "r"(a[0]), "r"(a[1]), "r"(a[2]), "r"(a[3]), "r"(b[0]), "r"(b[1]));
}
__device__ __forceinline__ void cp16(uint32_t smem_dst, const void* gptr) {
    asm volatile("cp.async.cg.shared.global [%0], [%1], 16;"
                 :: "r"(smem_dst), "l"(gptr));
}
__device__ __forceinline__ uint32_t pack_half2(__half a, __half b) {
    __half2 h2 = __halves2half2(a, b);
    return *(uint32_t*)&h2;
}

// ----------------- 1-pass fp16 mainloop, 128m x 128n x 64k -------------------
// 8 warps as 2(m) x 4(n): warp tile 64x32. acc[4][4][4].
// Stage (32 KB): Ah[16K] Bh[16K]; rows 128B, SW128. 2 stages = 64 KB -> 2 CTA/SM.
#define ST1_BH 16384
#define STAGE1 32768
#define GEMM1_SMEM (2*STAGE1)   // 65536

__device__ __forceinline__ void gemm_tile_1p(
    const __half* __restrict__ Ahp, size_t lda,
    const __half* __restrict__ Bhp, size_t ldb,
    int kIters, char* smem, float acc[4][4][4])
{
    const int tid = threadIdx.x;
    const int wid = tid >> 5, lane = tid & 31;
    const int wm = (wid & 1) * 64;      // warp m offset
    const int wn = (wid >> 1) * 32;     // warp n offset
    const uint32_t sbase = smem_to_u32(smem);

    const int r8 = tid >> 3, j8 = tid & 7;

    auto issue = [&](int c) {
        const int kc = c * 64;
        const uint32_t st = sbase + (c & 1) * STAGE1;
        #pragma unroll
        for (int i = 0; i < 4; i++) {
            const int r = r8 + i * 32;
            const uint32_t off = SW128((uint32_t)(r * 128 + j8 * 16));
            cp16(st + off,          Ahp + (size_t)r * lda + kc + j8 * 8);
            cp16(st + ST1_BH + off, Bhp + (size_t)r * ldb + kc + j8 * 8);
        }
        asm volatile("cp.async.commit_group;" ::: "memory");
    };

    const int a_row = (lane & 15);
    const int a_k8  = ((lane >> 4) & 1) * 8;
    const int b_row = (lane & 7) + ((lane >> 4) & 1) * 8;
    const int b_k8  = ((lane >> 3) & 1) * 8;

    issue(0);

    for (int c = 0; c < kIters; c++) {
        if (c + 1 < kIters) {
            issue(c + 1);
            asm volatile("cp.async.wait_group 1;" ::: "memory");
        } else {
            asm volatile("cp.async.wait_group 0;" ::: "memory");
        }
        __syncthreads();

        const uint32_t st = sbase + (c & 1) * STAGE1;
        #pragma unroll
        for (int ks = 0; ks < 4; ks++) {
            const int kbase = ks * 16;
            uint32_t ah[4][4];
            #pragma unroll
            for (int mi = 0; mi < 4; mi++) {
                const uint32_t off =
                    SW128((uint32_t)((wm + mi * 16 + a_row) * 128 + (kbase + a_k8) * 2));
                ldsm_x4(ah[mi], st + off);
            }
            uint32_t bh[4][2];
            #pragma unroll
            for (int p = 0; p < 2; p++) {
                const uint32_t off =
                    SW128((uint32_t)((wn + p * 16 + b_row) * 128 + (kbase + b_k8) * 2));
                uint32_t t[4];
                ldsm_x4(t, st + ST1_BH + off);
                bh[2 * p][0] = t[0]; bh[2 * p][1] = t[1];
                bh[2 * p + 1][0] = t[2]; bh[2 * p + 1][1] = t[3];
            }
            #pragma unroll
            for (int mi = 0; mi < 4; mi++)
                #pragma unroll
                for (int ni = 0; ni < 4; ni++)
                    mma_f16(acc[mi][ni], ah[mi], bh[ni]);
        }
        __syncthreads();
    }
}

// --------------------------- conversion kernels -----------------------------
__global__ __launch_bounds__(256) void convert_x(const float* __restrict__ x) {
    size_t i = ((size_t)blockIdx.x * 256 + threadIdx.x) * 4;
    float4 v = *(const float4*)(x + i);
    *(uint32_t*)(Xh + i)     = pack_half2(__float2half_rn(v.x), __float2half_rn(v.y));
    *(uint32_t*)(Xh + i + 2) = pack_half2(__float2half_rn(v.z), __float2half_rn(v.w));
}

// Transpose W: Wth[z][n][k] = fp16(W[z][k][n])
__global__ void convert_w(const float* __restrict__ Wq,
                          const float* __restrict__ Wk,
                          const float* __restrict__ Wv) {
    __shared__ float t[32][33];
    const int z = blockIdx.z;
    const float* W = (z == 0) ? Wq : ((z == 1) ? Wk : Wv);
    const int n0 = blockIdx.x * 32, k0 = blockIdx.y * 32;
    const int tx = threadIdx.x, ty = threadIdx.y;
    #pragma unroll
    for (int r = ty; r < 32; r += 8)
        t[r][tx] = W[(size_t)(k0 + r) * DIM + n0 + tx];
    __syncthreads();
    __half* oh = Wth + (size_t)z * DIM * DIM;
    #pragma unroll
    for (int r = ty; r < 32; r += 8)
        oh[(size_t)(n0 + r) * DIM + k0 + tx] = __float2half_rn(t[tx][r]);
}

// ---------------- QK GEMM: Q and K projections (1-pass, 128x128) -------------
__global__ __launch_bounds__(256) void qk_gemm() {
    extern __shared__ char smg[];
    const int tid = threadIdx.x;
    const int wid = tid >> 5, lane = tid & 31;
    const int n0 = blockIdx.x * 128, m0 = blockIdx.y * 128, z = blockIdx.z;
    const int wm = (wid & 1) * 64, wn = (wid >> 1) * 32;

    float acc[4][4][4] = {};
    gemm_tile_1p(Xh + (size_t)m0 * DIM, DIM,
                 Wth + (size_t)z * DIM * DIM + (size_t)n0 * DIM, DIM,
                 DIM / 64, smg, acc);

    __half* D = (z == 0) ? Qh : Kh;
    #pragma unroll
    for (int mi = 0; mi < 4; mi++) {
        const int row0 = m0 + wm + mi * 16 + (lane >> 2);
        #pragma unroll
        for (int ni = 0; ni < 4; ni++) {
            const int col = n0 + wn + ni * 8 + (lane & 3) * 2;
            #pragma unroll
            for (int half = 0; half < 2; half++) {
                const size_t idx = (size_t)(row0 + half * 8) * DIM + col;
                *(uint32_t*)(D + idx) = pack_half2(
                    __float2half_rn(acc[mi][ni][half * 2 + 0]),
                    __float2half_rn(acc[mi][ni][half * 2 + 1]));
            }
        }
    }
}

// ---------------- fused launch: S = Qh@Kh^T (triangular) + V projection -----
// grid (24, 16, 4): x<16 -> S-tile role (128x128); x>=16 -> V-projection role.
__global__ __launch_bounds__(256) void sv_gemm() {
    extern __shared__ char smg[];
    const int tid = threadIdx.x;
    const int wid = tid >> 5, lane = tid & 31;
    const int wm = (wid & 1) * 64, wn = (wid >> 1) * 32;

    if (blockIdx.x >= 16) {
        // ---- V projection role: vid in [0, 512) -> (m_blk 64, n_blk 8) ----
        const int vid = (blockIdx.x - 16) + 8 * (blockIdx.y + 16 * blockIdx.z);
        const int n0 = (vid & 7) * 128;
        const int m0 = (vid >> 3) * 128;

        float acc[4][4][4] = {};
        gemm_tile_1p(Xh + (size_t)m0 * DIM, DIM,
                     Wth + 2 * (size_t)DIM * DIM + (size_t)n0 * DIM, DIM,
                     DIM / 64, smg, acc);

        // transpose 32(d) x 64(s) warp tile via smem, write Vt[b][d][s]
        __syncthreads();
        __half* th = (__half*)smg + (size_t)wid * 32 * 66;
        #pragma unroll
        for (int mi = 0; mi < 4; mi++) {
            const int rl = mi * 16 + (lane >> 2);
            #pragma unroll
            for (int ni = 0; ni < 4; ni++) {
                const int cl = ni * 8 + (lane & 3) * 2;
                #pragma unroll
                for (int half = 0; half < 2; half++) {
                    const int r = rl + half * 8;
                    th[(cl + 0) * 66 + r] = __float2half_rn(acc[mi][ni][half * 2 + 0]);
                    th[(cl + 1) * 66 + r] = __float2half_rn(acc[mi][ni][half * 2 + 1]);
                }
            }
        }
        __syncwarp();
        const int b    = m0 >> 11;
        const int sloc = (m0 & (SEQ - 1)) + wm;
        __half* vth = Vth + (size_t)b * DIM * SEQ;
        #pragma unroll 4
        for (int c = 0; c < 32; c++) {
            *(uint32_t*)(vth + (size_t)(n0 + wn + c) * SEQ + sloc + lane * 2) =
                *(uint32_t*)(th + c * 66 + lane * 2);
        }
        return;
    }

    // ---- S role (triangular, heavy tiles first, scale fused) ----
    const int bn = blockIdx.x;
    const int bm = gridDim.y - 1 - blockIdx.y;
    const int b  = blockIdx.z;
    if (bn > bm) return;                 // tile fully above diagonal
    const int m0 = bm * 128, n0 = bn * 128;

    const size_t boff = (size_t)b * SEQ * DIM;
    float acc[4][4][4] = {};
    gemm_tile_1p(Qh + boff + (size_t)m0 * DIM, DIM,
                 Kh + boff + (size_t)n0 * DIM, DIM,
                 DIM / 64, smg, acc);

    float* S = Sg + (size_t)b * SEQ * SEQ;
    const float scale = 0.03125f;
    #pragma unroll
    for (int mi = 0; mi < 4; mi++) {
        const int row0 = m0 + wm + mi * 16 + (lane >> 2);
        #pragma unroll
        for (int ni = 0; ni < 4; ni++) {
            const int col = n0 + wn + ni * 8 + (lane & 3) * 2;
            *(float2*)(S + (size_t)row0 * SEQ + col) =
                make_float2(acc[mi][ni][0] * scale, acc[mi][ni][1] * scale);
            *(float2*)(S + (size_t)(row0 + 8) * SEQ + col) =
                make_float2(acc[mi][ni][2] * scale, acc[mi][ni][3] * scale);
        }
    }
}

// ---------------- softmax: Sg -> Ph (fp16 only) ------------------------------
// No max pass: scores are pre-scaled and bounded, exp() is safe in fp32.
__global__ __launch_bounds__(256) void softmax_split() {
    __shared__ float4 ebuf4[SEQ / 4];
    __shared__ float red[8];
    const int q = blockIdx.x, b = blockIdx.y;
    const int rowpad4 = (((q >> 7) << 7) + 128) >> 2;
    const int tid = threadIdx.x, wid = tid >> 5, lane = tid & 31;

    const float4* srow4 = (const float4*)(Sg + ((size_t)b * SEQ + q) * SEQ);

    float sum = 0.0f;
    for (int i = tid; i < rowpad4; i += 256) {
        const float4 s4 = srow4[i];
        const int base = i * 4;
        float4 e;
        e.x = (base + 0 <= q) ? __expf(s4.x) : 0.0f;
        e.y = (base + 1 <= q) ? __expf(s4.y) : 0.0f;
        e.z = (base + 2 <= q) ? __expf(s4.z) : 0.0f;
        e.w = (base + 3 <= q) ? __expf(s4.w) : 0.0f;
        ebuf4[i] = e;
        sum += (e.x + e.y) + (e.z + e.w);
    }
    #pragma unroll
    for (int o = 16; o; o >>= 1) sum += __shfl_xor_sync(0xffffffffu, sum, o);
    if (lane == 0) red[wid] = sum;
    __syncthreads();
    float s2 = red[0];
    #pragma unroll
    for (int i = 1; i < 8; i++) s2 += red[i];
    const float inv = 1.0f / s2;

    uint2* ph = (uint2*)(Ph + ((size_t)b * SEQ + q) * SEQ);
    for (int i = tid; i < rowpad4; i += 256) {
        const float4 e = ebuf4[i];
        ph[i] = make_uint2(
            pack_half2(__float2half_rn(e.x * inv), __float2half_rn(e.y * inv)),
            pack_half2(__float2half_rn(e.z * inv), __float2half_rn(e.w * inv)));
    }
}

// ---------------- O GEMM: out = Ph @ V (1-pass, causal k-range) --------------
__global__ __launch_bounds__(256) void o_gemm(float* __restrict__ out) {
    extern __shared__ char smg[];
    const int tid = threadIdx.x;
    const int wid = tid >> 5, lane = tid & 31;
    const int bn = blockIdx.x;
    const int bm = gridDim.y - 1 - blockIdx.y;   // heavy rows first
    const int b  = blockIdx.z;
    const int m0 = bm * 128, n0 = bn * 128;
    const int wm = (wid & 1) * 64, wn = (wid >> 1) * 32;

    const size_t poff = (size_t)b * SEQ * SEQ;
    const size_t voff = (size_t)b * DIM * SEQ;
    float acc[4][4][4] = {};
    gemm_tile_1p(Ph + poff + (size_t)m0 * SEQ, SEQ,
                 Vth + voff + (size_t)n0 * SEQ, SEQ,
                 (m0 + 128) / 64, smg, acc);

    float* O = out + (size_t)b * SEQ * DIM;
    #pragma unroll
    for (int mi = 0; mi < 4; mi++) {
        const int row0 = m0 + wm + mi * 16 + (lane >> 2);
        #pragma unroll
        for (int ni = 0; ni < 4; ni++) {
            const int col = n0 + wn + ni * 8 + (lane & 3) * 2;
            *(float2*)(O + (size_t)row0 * DIM + col) =
                make_float2(acc[mi][ni][0], acc[mi][ni][1]);
            *(float2*)(O + (size_t)(row0 + 8) * DIM + col) =
                make_float2(acc[mi][ni][2], acc[mi][ni][3]);
        }
    }
}

// ---------------------------------------------------------------------------
extern "C" void kernel_launch(void* const* d_in, const int* in_sizes, int n_in,
                              void* d_out, int out_size)
{
    const float* x  = (const float*)d_in[0];
    const float* Wq = (const float*)d_in[1];
    const float* Wk = (const float*)d_in[2];
    const float* Wv = (const float*)d_in[3];
    float* out = (float*)d_out;

    cudaFuncSetAttribute(qk_gemm, cudaFuncAttributeMaxDynamicSharedMemorySize, GEMM1_SMEM);
    cudaFuncSetAttribute(sv_gemm, cudaFuncAttributeMaxDynamicSharedMemorySize, GEMM1_SMEM);
    cudaFuncSetAttribute(o_gemm,  cudaFuncAttributeMaxDynamicSharedMemorySize, GEMM1_SMEM);

    // fp32 -> fp16
    convert_x<<<MTOT * DIM / (256 * 4), 256>>>(x);
    convert_w<<<dim3(DIM / 32, DIM / 32, 3), dim3(32, 8)>>>(Wq, Wk, Wv);

    // Q + K projections (128x128 tiles)
    qk_gemm<<<dim3(DIM / 128, MTOT / 128, 2), 256, GEMM1_SMEM>>>();

    // Fused: S scores (triangular, scaled) + V projection (transposed write)
    sv_gemm<<<dim3(24, 16, BATCH), 256, GEMM1_SMEM>>>();

    // Softmax (no max pass) -> Ph
    softmax_split<<<dim3(SEQ, BATCH), 256>>>();

    // O = Ph @ V (causal k-range)
    o_gemm<<<dim3(DIM / 128, SEQ / 128, BATCH), 256, GEMM1_SMEM>>>(out);
}